// round 8
// baseline (speedup 1.0000x reference)
#include <cuda_runtime.h>
#include <cuda_fp16.h>
#include <cstdint>

#define BTOK 262144
#define DM 128
#define DFF 512
#define NT 16
#define NOPS 8
#define EMB 32
#define MROWS 128
#define SLDH 136
#define MAXBLK (BTOK/MROWS + NT)
#define TSTR (BTOK + 128)

// ---------------- device scratch ----------------
__device__ float g_Tf[NOPS*DM];
__device__ float g_Tg[256*DM];
__device__ float g_Th[256*DM];
__device__ float g_Lf[NOPS*NT];
__device__ float g_Lg[256*NT];
__device__ float g_Lh[256*NT];
__device__ float g_Lc[NT];
__device__ float g_Lb[NT];
__device__ float g_s1[NT], g_s2[NT];
__device__ double g_sabs[32];
__device__ double g_res[2];
__device__ __half g_W1h[NT*DFF*DM];   // [t][n(dff)][k(d)]
__device__ __half g_W2h[NT*DM*DFF];   // [t][n(d)][k(dff)]
__device__ double g_sumP[NT];
__device__ int g_fill[NT];
__device__ int g_nblocks;
__device__ float g_gate[BTOK];
__device__ int g_src[NT*TSTR];
__device__ int g_bmT[MAXBLK];
__device__ int g_bmR[MAXBLK];

// ---------------- helpers ----------------
__device__ __forceinline__ float tanh_fast(float v){
    float r; asm("tanh.approx.f32 %0, %1;" : "=f"(r) : "f"(v)); return r;
}
__device__ __forceinline__ uint32_t smem_u32(const void* p){
    uint32_t a;
    asm("{ .reg .u64 t; cvta.to.shared.u64 t, %1; cvt.u32.u64 %0, t; }":"=r"(a):"l"(p));
    return a;
}
__device__ __forceinline__ void ldsm4(uint32_t* r, uint32_t addr){
    asm volatile("ldmatrix.sync.aligned.m8n8.x4.shared.b16 {%0,%1,%2,%3}, [%4];"
        : "=r"(r[0]),"=r"(r[1]),"=r"(r[2]),"=r"(r[3]) : "r"(addr));
}
__device__ __forceinline__ void mma16(float* c, const uint32_t* a, const uint32_t* b){
    asm volatile("mma.sync.aligned.m16n8k16.row.col.f32.f16.f16.f32 "
        "{%0,%1,%2,%3},{%4,%5,%6,%7},{%8,%9},{%0,%1,%2,%3};"
        : "+f"(c[0]),"+f"(c[1]),"+f"(c[2]),"+f"(c[3])
        : "r"(a[0]),"r"(a[1]),"r"(a[2]),"r"(a[3]),"r"(b[0]),"r"(b[1]));
}
// fp16-accumulate mma, zero-init per call, promoted into fp32 regs
__device__ __forceinline__ void mma16h_acc(float* c, const uint32_t* a, const uint32_t* b){
    uint32_t d0, d1;
    asm volatile("mma.sync.aligned.m16n8k16.row.col.f16.f16.f16.f16 "
        "{%0,%1},{%2,%3,%4,%5},{%6,%7},{%8,%8};"
        : "=r"(d0),"=r"(d1)
        : "r"(a[0]),"r"(a[1]),"r"(a[2]),"r"(a[3]),"r"(b[0]),"r"(b[1]),"r"(0u));
    float2 f0 = __half22float2(*(__half2*)&d0);
    float2 f1 = __half22float2(*(__half2*)&d1);
    c[0]+=f0.x; c[1]+=f0.y; c[2]+=f1.x; c[3]+=f1.y;
}
__device__ __forceinline__ __half2 h2pack(float a, float b){
    return __floats2half2_rn(a, b);
}
__device__ __forceinline__ void cpa16(uint32_t dst, const void* src){
    asm volatile("cp.async.cg.shared.global [%0], [%1], 16;" :: "r"(dst),"l"(src):"memory");
}
__device__ __forceinline__ void cpa_commit(){
    asm volatile("cp.async.commit_group;":::"memory");
}
__device__ __forceinline__ void cpa_wait0(){
    asm volatile("cp.async.wait_group 0;":::"memory");
}

// ---------------- k_init ----------------
__global__ void k_init(){
    int i = threadIdx.x;
    if (i < NT){ g_sumP[i]=0.0; g_fill[i]=0; }
    if (i < 32) g_sabs[i]=0.0;
    if (i < 2)  g_res[i]=0.0;
}

// ---------------- k_tables ----------------
__global__ void k_tables(const float* __restrict__ oe, const float* __restrict__ Win){
    int gid = blockIdx.x*256 + threadIdx.x;
    if (gid < 32768){
        int av = gid >> 7, d = gid & 127;
        float s = 0.f;
        #pragma unroll
        for (int i=0;i<8;i++) if ((av>>i)&1) s += Win[(32+i)*DM + d];
        g_Tg[av*DM+d] = s;
    } else if (gid < 65536){
        int g2 = gid - 32768;
        int bv = g2 >> 7, d = g2 & 127;
        float s = 0.f;
        #pragma unroll
        for (int i=0;i<8;i++) if ((bv>>i)&1) s += Win[(40+i)*DM + d];
        g_Th[bv*DM+d] = s;
    } else if (gid < 66560){
        int g2 = gid - 65536;
        int op = g2 >> 7, d = g2 & 127;
        float s = 0.f;
        #pragma unroll
        for (int j=0;j<EMB;j++) s += oe[op*EMB+j]*Win[j*DM+d];
        g_Tf[op*DM+d] = s;
    }
}

// ---------------- k_lt ----------------
__global__ void k_lt(const float* __restrict__ Wr, const float* __restrict__ Win,
                     const float* __restrict__ bin){
    int gid = blockIdx.x*256+threadIdx.x;
    if (gid < 4096){
        int av=gid>>4, t=gid&15; float s=0.f;
        for(int d=0;d<DM;d++) s += g_Tg[av*DM+d]*Wr[d*NT+t];
        g_Lg[gid]=s;
    } else if (gid < 8192){
        int g2=gid-4096; int bv=g2>>4,t=g2&15; float s=0.f;
        for(int d=0;d<DM;d++) s += g_Th[bv*DM+d]*Wr[d*NT+t];
        g_Lh[g2]=s;
    } else if (gid < 8320){
        int g2=gid-8192; int op=g2>>4,t=g2&15; float s=0.f;
        for(int d=0;d<DM;d++) s += g_Tf[op*DM+d]*Wr[d*NT+t];
        g_Lf[g2]=s;
    } else if (gid < 8336){
        int t=gid-8320; float s=0.f;
        for(int d=0;d<DM;d++) s += Win[48*DM+d]*Wr[d*NT+t];
        g_Lc[t]=s;
    } else if (gid < 8352){
        int t=gid-8336; float s=0.f;
        for(int d=0;d<DM;d++) s += bin[d]*Wr[d*NT+t];
        g_Lb[t]=s;
    }
}

// ---------------- k_scalep ----------------
__global__ void k_scalep(const float* __restrict__ W1, const float* __restrict__ W2){
    __shared__ double red[256];
    int tile = blockIdx.x >> 4;
    int sub  = blockIdx.x & 15;
    const float* W = (tile < 16 ? W1 + tile*65536 : W2 + (tile-16)*65536) + sub*4096;
    const float4* W4 = (const float4*)W;
    double s = 0.0;
    #pragma unroll
    for (int r=0;r<4;r++){
        float4 v = W4[threadIdx.x + r*256];
        s += (double)(fabsf(v.x)+fabsf(v.y)+fabsf(v.z)+fabsf(v.w));
    }
    red[threadIdx.x]=s; __syncthreads();
    for (int o=128;o;o>>=1){ if(threadIdx.x<o) red[threadIdx.x]+=red[threadIdx.x+o]; __syncthreads(); }
    if (!threadIdx.x) atomicAdd(&g_sabs[tile], red[0]);
}

// ---------------- k_sfin ----------------
__global__ void k_sfin(){
    int t = threadIdx.x;
    if (t < 16) g_s1[t] = (float)(g_sabs[t]/65536.0);
    else if (t < 32) g_s2[t-16] = (float)(g_sabs[t]/65536.0);
}

// ---------------- k_quant: coalesced transpose via smem ----------------
// blocks 0..127: W1, tile t=b>>3, n0=(b&7)*64 ; region k[0,128) x n[n0,n0+64)
// blocks 128..255: W2, tile t, kk0=(b&7)*64 ; region kk[kk0,kk0+64) x nn[0,128)
__global__ void k_quant(const float* __restrict__ W1, const float* __restrict__ W2){
    __shared__ __half sh[64*130];
    __shared__ double red[256];
    int b = blockIdx.x, tid = threadIdx.x;
    double racc = 0.0;
    if (b < 128){
        int t = b>>3, n0 = (b&7)*64;
        float s = g_s1[t];
        const float* src = W1 + t*65536;
        #pragma unroll
        for (int j=0;j<32;j++){
            int i = tid + j*256;          // 8192 elems
            int k = i>>6, nx = i&63;
            float w = src[k*512 + n0 + nx];
            float aw = fabsf(w);
            bool nz = aw > 0.7f*s;
            float q = nz ? (w>0.f?1.f:-1.f) : 0.f;
            racc += (double)(nz ? fabsf(aw - s) : aw);
            sh[nx*130 + k] = __float2half(q);
        }
        __syncthreads();
        __half* dst = g_W1h + t*65536 + n0*128;
        #pragma unroll
        for (int j=0;j<32;j++){
            int i = tid + j*256;
            int n = i>>7, k = i&127;
            dst[n*128 + k] = sh[n*130 + k];
        }
        red[tid]=racc; __syncthreads();
        for(int o=128;o;o>>=1){ if(tid<o) red[tid]+=red[tid+o]; __syncthreads(); }
        if (!tid) atomicAdd(&g_res[0], red[0]);
    } else {
        int bb = b-128;
        int t = bb>>3, kk0 = (bb&7)*64;
        float s = g_s2[t];
        const float* src = W2 + t*65536;
        #pragma unroll
        for (int j=0;j<32;j++){
            int i = tid + j*256;
            int kk = i>>7, nn = i&127;
            float w = src[(kk0+kk)*128 + nn];
            float aw = fabsf(w);
            bool nz = aw > 0.7f*s;
            float q = nz ? (w>0.f?1.f:-1.f) : 0.f;
            racc += (double)(nz ? fabsf(aw - s) : aw);
            sh[kk*130 + nn] = __float2half(q);
        }
        __syncthreads();
        __half* dst = g_W2h + t*65536 + kk0;
        #pragma unroll
        for (int j=0;j<32;j++){
            int i = tid + j*256;
            int nn = i>>6, kx = i&63;
            dst[nn*512 + kx] = sh[kx*130 + nn];
        }
        red[tid]=racc; __syncthreads();
        for(int o=128;o;o>>=1){ if(tid<o) red[tid]+=red[tid+o]; __syncthreads(); }
        if (!tid) atomicAdd(&g_res[1], red[0]);
    }
}

// ---------------- k_route: logits, softmax, argmax, stats, fused scatter ----------------
__global__ void k_route(const int* __restrict__ op, const int* __restrict__ a,
                        const int* __restrict__ b, const int* __restrict__ c,
                        float* __restrict__ outIdx){
    __shared__ float sLf[NOPS*NT], sLg[256*NT], sLh[256*NT], sLc[NT], sLb[NT];
    __shared__ float sP[NT]; __shared__ int sC[NT]; __shared__ int sBase[NT];
    int tid = threadIdx.x;
    int lane = tid & 31;
    for (int i=tid;i<256*NT;i+=256){ sLg[i]=g_Lg[i]; sLh[i]=g_Lh[i]; }
    for (int i=tid;i<NOPS*NT;i+=256) sLf[i]=g_Lf[i];
    if (tid<NT){ sLc[tid]=g_Lc[tid]; sLb[tid]=g_Lb[tid]; sP[tid]=0.f; sC[tid]=0; }
    __syncthreads();
    int i = blockIdx.x*256+tid;
    int opv=op[i], av=a[i], bv=b[i]; float cv=(float)c[i];
    float l[NT]; float mx=-1e30f; int best=0;
    #pragma unroll
    for (int t=0;t<NT;t++){
        float v = sLf[opv*NT+t]+sLg[av*NT+t]+sLh[bv*NT+t]+cv*sLc[t]+sLb[t];
        l[t]=v;
        if (v>mx){mx=v;best=t;}
    }
    float den=0.f;
    #pragma unroll
    for (int t=0;t<NT;t++){ l[t]=__expf(l[t]-mx); den+=l[t]; }
    float inv = 1.f/den;
    #pragma unroll
    for (int t=0;t<NT;t++){
        float v = l[t]*inv;
        #pragma unroll
        for (int o=16;o;o>>=1) v += __shfl_xor_sync(0xffffffffu, v, o);
        if (lane==0) atomicAdd(&sP[t], v);
    }
    int rank = atomicAdd(&sC[best], 1);
    g_gate[i]=inv; outIdx[i]=(float)best;
    __syncthreads();
    if (tid<NT){
        sBase[tid] = atomicAdd(&g_fill[tid], sC[tid]);
        atomicAdd(&g_sumP[tid], (double)sP[tid]);
    }
    __syncthreads();
    g_src[best*TSTR + sBase[best] + rank] = i;
}

// ---------------- k_part (parallel fill) ----------------
__global__ void k_part(){
    __shared__ int pc[NT], po_[NT];
    int tid=threadIdx.x;
    if (tid<NT) pc[tid] = g_fill[tid];
    __syncthreads();
    if (tid==0){
        int nb=0;
        for (int t=0;t<NT;t++){ po_[t]=nb; nb += (pc[t]+MROWS-1)/MROWS; }
        g_nblocks = nb;
    }
    __syncthreads();
    for (int t=0;t<NT;t++){
        int bl = (pc[t]+MROWS-1)/MROWS;
        for (int bi=tid; bi<bl; bi+=256){ g_bmT[po_[t]+bi]=t; g_bmR[po_[t]+bi]=t*TSTR + bi*MROWS; }
        int cnt=pc[t]; int pad = bl*MROWS;
        for (int p=cnt+tid; p<pad; p+=256) g_src[t*TSTR+p] = -1;
    }
}

// ---------------- k_ffn: 256 threads, fp16-acc mma + ldmatrix + cp.async pipeline ----------------
__global__ void __launch_bounds__(256,1) k_ffn(
    const int* __restrict__ op, const int* __restrict__ aIn,
    const int* __restrict__ bIn, const int* __restrict__ cIn,
    const float* __restrict__ Win, const float* __restrict__ bin,
    const float* __restrict__ Wh1, const float* __restrict__ bh1,
    const float* __restrict__ Wh2, const float* __restrict__ bh2,
    float* __restrict__ outR)
{
    extern __shared__ __half sm[];
    __half* sX  = sm;
    __half* sW0 = sm + 128*SLDH;
    __half* sW1 = sm + 2*128*SLDH;
    __half* sG  = sm + 3*128*SLDH;
    __shared__ float sGate[MROWS];
    __shared__ int   sSrc[MROWS];
    __shared__ float sWh2[512], sbh1[64], sbh2[8];

    int bid = blockIdx.x;
    if (bid >= g_nblocks) return;
    int t  = g_bmT[bid], r0 = g_bmR[bid];
    int tid = threadIdx.x;
    int wid = tid>>5, lane = tid&31;
    int grp = lane>>2, tq = lane&3;
    int wm = wid&3, wn = wid>>2;            // 4 m-warps x 2 n-warps
    float s1 = g_s1[t], s2 = g_s2[t];

    uint32_t bX = smem_u32(sX), bG = smem_u32(sG);
    uint32_t bufs[2] = { smem_u32(sW0), smem_u32(sW1) };
    uint32_t aoff  = (uint32_t)((lane&15)*SLDH + (lane>>4)*8)*2;
    uint32_t boff4 = (uint32_t)(((lane&7) + ((lane>>4)<<3))*SLDH + ((lane>>3)&1)*8)*2;

    const __half* W1p = g_W1h + t*65536;
    const __half* W2p = g_W2h + t*65536;

    // ---- prefetch stage 0 (W1 chunk 0) ----
    {
        #pragma unroll
        for (int j=0;j<8;j++){
            int i = tid + j*256;
            int row = i>>4, ck = i&15;
            cpa16(bufs[0] + (uint32_t)(row*SLDH + ck*8)*2, W1p + row*128 + ck*8);
        }
        cpa_commit();
    }

    // ---- build X tile (fp16); 2 threads/row ----
    {
        int row = tid>>1, half = tid&1;
        int token = g_src[r0+row];
        if (half==0){ sSrc[row]=token; sGate[row]=(token>=0)?g_gate[token]:0.f; }
        const float* wc = Win + 48*DM;
        __half* dst = sX + row*SLDH + half*64;
        if (token>=0){
            int opv=op[token], av=aIn[token], bv=bIn[token]; float cv=(float)cIn[token];
            const float* tf=&g_Tf[opv*DM+half*64]; const float* tg=&g_Tg[av*DM+half*64];
            const float* th=&g_Th[bv*DM+half*64];
            const float* wcc=wc+half*64; const float* bb=bin+half*64;
            #pragma unroll 8
            for (int d=0; d<64; d+=2){
                float x0 = tf[d]+tg[d]+th[d]+cv*wcc[d]+bb[d];
                float x1 = tf[d+1]+tg[d+1]+th[d+1]+cv*wcc[d+1]+bb[d+1];
                *(__half2*)(dst+d) = h2pack(x0,x1);
            }
        } else {
            #pragma unroll 8
            for (int d=0; d<64; d+=2) *(uint32_t*)(dst+d) = 0u;
        }
    }
    for (int i=tid;i<512;i+=256) sWh2[i]=Wh2[i];
    if (tid<64) sbh1[tid]=bh1[tid];
    if (tid<8)  sbh2[tid]=bh2[tid];

    float c2[2][8][4];
    #pragma unroll
    for(int mt=0;mt<2;mt++)
        #pragma unroll
        for(int nt=0;nt<8;nt++)
            #pragma unroll
            for(int e=0;e<4;e++) c2[mt][nt][e]=0.f;

    cpa_wait0();
    __syncthreads();

    for (int s=0;s<8;s++){
        if (s<7){
            int sn = s+1, ch = sn>>1;
            uint32_t dstb = bufs[sn&1];
            if (!(sn&1)){
                const __half* src = W1p + ch*16384;
                #pragma unroll
                for (int j=0;j<8;j++){
                    int i = tid + j*256;
                    int row = i>>4, ck = i&15;
                    cpa16(dstb + (uint32_t)(row*SLDH + ck*8)*2, src + row*128 + ck*8);
                }
            } else {
                const __half* src = W2p + ch*128;
                #pragma unroll
                for (int j=0;j<8;j++){
                    int i = tid + j*256;
                    int row = i>>4, ck = i&15;
                    cpa16(dstb + (uint32_t)(row*SLDH + ck*8)*2, src + row*512 + ck*8);
                }
            }
            cpa_commit();
        }
        uint32_t bw = bufs[s&1];
        if (!(s&1)){
            float c1[2][8][4];
            #pragma unroll
            for(int mt=0;mt<2;mt++)
                #pragma unroll
                for(int nt=0;nt<8;nt++)
                    #pragma unroll
                    for(int e=0;e<4;e++) c1[mt][nt][e]=0.f;
            #pragma unroll
            for (int kk=0;kk<8;kk++){
                uint32_t af[2][4];
                ldsm4(af[0], bX + aoff + (uint32_t)((wm*32)*SLDH + kk*16)*2);
                ldsm4(af[1], bX + aoff + (uint32_t)((wm*32+16)*SLDH + kk*16)*2);
                #pragma unroll
                for (int ntp=0;ntp<4;ntp++){
                    uint32_t bq[4];
                    ldsm4(bq, bw + boff4 + (uint32_t)((wn*64+ntp*16)*SLDH + kk*16)*2);
                    mma16h_acc(c1[0][2*ntp],   af[0], bq);
                    mma16h_acc(c1[1][2*ntp],   af[1], bq);
                    mma16h_acc(c1[0][2*ntp+1], af[0], bq+2);
                    mma16h_acc(c1[1][2*ntp+1], af[1], bq+2);
                }
            }
            #pragma unroll
            for (int mt=0;mt<2;mt++){
                int row0 = wm*32+mt*16+grp;
                #pragma unroll
                for (int nt=0;nt<8;nt++){
                    int col = wn*64+nt*8+2*tq;
                    float v0=s1*c1[mt][nt][0], v1=s1*c1[mt][nt][1];
                    float v2=s1*c1[mt][nt][2], v3=s1*c1[mt][nt][3];
                    float g0 = 0.5f*v0*(1.f+tanh_fast(0.7978845608f*(v0+0.044715f*v0*v0*v0)));
                    float g1 = 0.5f*v1*(1.f+tanh_fast(0.7978845608f*(v1+0.044715f*v1*v1*v1)));
                    float g2 = 0.5f*v2*(1.f+tanh_fast(0.7978845608f*(v2+0.044715f*v2*v2*v2)));
                    float g3 = 0.5f*v3*(1.f+tanh_fast(0.7978845608f*(v3+0.044715f*v3*v3*v3)));
                    *(__half2*)(sG + row0*SLDH + col)     = h2pack(g0,g1);
                    *(__half2*)(sG + (row0+8)*SLDH + col) = h2pack(g2,g3);
                }
            }
        } else {
            #pragma unroll
            for (int kk=0;kk<8;kk++){
                uint32_t af[2][4];
                ldsm4(af[0], bG + aoff + (uint32_t)((wm*32)*SLDH + kk*16)*2);
                ldsm4(af[1], bG + aoff + (uint32_t)((wm*32+16)*SLDH + kk*16)*2);
                #pragma unroll
                for (int ntp=0;ntp<4;ntp++){
                    uint32_t bq[4];
                    ldsm4(bq, bw + boff4 + (uint32_t)((wn*64+ntp*16)*SLDH + kk*16)*2);
                    mma16h_acc(c2[0][2*ntp],   af[0], bq);
                    mma16h_acc(c2[1][2*ntp],   af[1], bq);
                    mma16h_acc(c2[0][2*ntp+1], af[0], bq+2);
                    mma16h_acc(c2[1][2*ntp+1], af[1], bq+2);
                }
            }
        }
        cpa_wait0();
        __syncthreads();
    }

    // ---- gated output -> sX (head A, fp16) ----
    #pragma unroll
    for (int mt=0;mt<2;mt++){
        int row0 = wm*32+mt*16+grp;
        float ga = sGate[row0], gb = sGate[row0+8];
        #pragma unroll
        for (int nt=0;nt<8;nt++){
            int col = wn*64+nt*8+2*tq;
            *(__half2*)(sX + row0*SLDH + col)     = h2pack(s2*c2[mt][nt][0]*ga, s2*c2[mt][nt][1]*ga);
            *(__half2*)(sX + (row0+8)*SLDH + col) = h2pack(s2*c2[mt][nt][2]*gb, s2*c2[mt][nt][3]*gb);
        }
    }
    // ---- Wh1^T -> sW0 [64 n][128 k] ----
    for (int i=tid; i<64*64; i+=256){
        int n = i>>6, k = (i&63)*2;
        *(__half2*)(sW0 + n*SLDH + k) = h2pack(Wh1[k*64+n], Wh1[(k+1)*64+n]);
    }
    __syncthreads();
    // ---- head GEMM: [128x128] @ [64x128]^T (fp32 accum) ----
    uint32_t bw0 = bufs[0];
    float c3[2][4][4];
    #pragma unroll
    for(int mt=0;mt<2;mt++)
        #pragma unroll
        for(int nt=0;nt<4;nt++)
            #pragma unroll
            for(int e=0;e<4;e++) c3[mt][nt][e]=0.f;
    #pragma unroll
    for (int kk=0;kk<8;kk++){
        uint32_t af[2][4];
        ldsm4(af[0], bX + aoff + (uint32_t)((wm*32)*SLDH + kk*16)*2);
        ldsm4(af[1], bX + aoff + (uint32_t)((wm*32+16)*SLDH + kk*16)*2);
        #pragma unroll
        for (int ntp=0;ntp<2;ntp++){
            uint32_t bq[4];
            ldsm4(bq, bw0 + boff4 + (uint32_t)((wn*32+ntp*16)*SLDH + kk*16)*2);
            mma16(c3[0][2*ntp],   af[0], bq);
            mma16(c3[1][2*ntp],   af[1], bq);
            mma16(c3[0][2*ntp+1], af[0], bq+2);
            mma16(c3[1][2*ntp+1], af[1], bq+2);
        }
    }
    __syncthreads();
    // ---- h = relu(c3+bh1) -> float buffer (reuse sX) ----
    float* sH = (float*)sX;   // [128][66]
    #pragma unroll
    for (int mt=0;mt<2;mt++){
        int row0 = wm*32+mt*16+grp;
        #pragma unroll
        for (int nt=0;nt<4;nt++){
            int col = wn*32+nt*8+2*tq;
            sH[row0*66+col]       = fmaxf(c3[mt][nt][0]+sbh1[col],   0.f);
            sH[row0*66+col+1]     = fmaxf(c3[mt][nt][1]+sbh1[col+1], 0.f);
            sH[(row0+8)*66+col]   = fmaxf(c3[mt][nt][2]+sbh1[col],   0.f);
            sH[(row0+8)*66+col+1] = fmaxf(c3[mt][nt][3]+sbh1[col+1], 0.f);
        }
    }
    __syncthreads();
    // ---- final 64->8 + sigmoid (2 threads/row) ----
    {
        int row = tid>>1, c0 = (tid&1)*4;
        int token = sSrc[row];
        if (token>=0){
            float acc0=sbh2[c0], acc1=sbh2[c0+1], acc2=sbh2[c0+2], acc3=sbh2[c0+3];
            #pragma unroll 8
            for (int k2=0;k2<64;k2++){
                float hv = sH[row*66+k2];
                acc0 += hv*sWh2[k2*8+c0];
                acc1 += hv*sWh2[k2*8+c0+1];
                acc2 += hv*sWh2[k2*8+c0+2];
                acc3 += hv*sWh2[k2*8+c0+3];
            }
            float* o = outR + (size_t)token*8 + c0;
            o[0] = 1.f/(1.f+__expf(-acc0));
            o[1] = 1.f/(1.f+__expf(-acc1));
            o[2] = 1.f/(1.f+__expf(-acc2));
            o[3] = 1.f/(1.f+__expf(-acc3));
        }
    }
}

// ---------------- k_aux ----------------
__global__ void k_aux(float* __restrict__ aux){
    if (threadIdx.x==0){
        double sp=0.0, cp[4]={0,0,0,0};
        for (int t=0;t<NT;t++){
            double frac = (double)g_fill[t]/(double)BTOK;
            double mp = g_sumP[t]/(double)BTOK;
            sp += frac*mp;
            cp[t>>2] += mp;
        }
        double sparsity = 16.0*sp;
        double tern = g_res[0]/1048576.0 + g_res[1]/1048576.0;
        double divv = 0.0;
        for (int i=0;i<4;i++) divv += cp[i]*log(cp[i]+1e-9);
        aux[0] = (float)(0.01*tern + 0.005*sparsity + 0.01*divv);
    }
}

// ---------------- launch ----------------
extern "C" void kernel_launch(void* const* d_in, const int* in_sizes, int n_in,
                              void* d_out, int out_size){
    const int *op=nullptr,*a=nullptr,*b=nullptr,*c=nullptr;
    const float *oe=nullptr,*Win=nullptr,*bin=nullptr,*Wr=nullptr,*W1=nullptr,*W2=nullptr;
    const float *Wh1=nullptr,*bh1=nullptr,*Wh2=nullptr,*bh2=nullptr;
    int nb_=0, nw=0;
    for (int i=0;i<n_in;i++){
        int s = in_sizes[i]; void* p = (void*)d_in[i];
        switch(s){
            case BTOK:
                if(nb_==0) op=(const int*)p; else if(nb_==1) a=(const int*)p;
                else if(nb_==2) b=(const int*)p; else c=(const int*)p;
                nb_++; break;
            case 256:  oe=(const float*)p; break;
            case 6272: Win=(const float*)p; break;
            case 128:  bin=(const float*)p; break;
            case 2048: Wr=(const float*)p; break;
            case 1048576: if(nw==0) W1=(const float*)p; else W2=(const float*)p; nw++; break;
            case 8192: Wh1=(const float*)p; break;
            case 64:   bh1=(const float*)p; break;
            case 512:  Wh2=(const float*)p; break;
            case 8:    bh2=(const float*)p; break;
            default: break;
        }
    }
    float* out = (float*)d_out;
    int smem = 4*128*SLDH*2;
    cudaFuncSetAttribute(k_ffn, cudaFuncAttributeMaxDynamicSharedMemorySize, smem);

    k_init<<<1,32>>>();
    k_tables<<<260,256>>>(oe,Win);
    k_lt<<<33,256>>>(Wr,Win,bin);
    k_scalep<<<512,256>>>(W1,W2);
    k_sfin<<<1,32>>>();
    k_quant<<<256,256>>>(W1,W2);
    k_route<<<BTOK/256,256>>>(op,a,b,c,out + (size_t)BTOK*8);
    k_part<<<1,256>>>();
    k_ffn<<<MAXBLK,256,smem>>>(op,a,b,c,Win,bin,Wh1,bh1,Wh2,bh2,out);
    k_aux<<<1,32>>>(out + (size_t)BTOK*9);
}

// round 9
// speedup vs baseline: 1.0002x; 1.0002x over previous
#include <cuda_runtime.h>
#include <cuda_fp16.h>
#include <cstdint>

#define BTOK 262144
#define DM 128
#define DFF 512
#define NT 16
#define NOPS 8
#define EMB 32
#define MROWS 128
#define SLDH 136
#define MAXBLK (BTOK/MROWS + NT)
#define TSTR (BTOK + 128)

// ---------------- device scratch ----------------
__device__ float g_Tf[NOPS*DM];
__device__ float g_Tg[256*DM];
__device__ float g_Th[256*DM];
__device__ float g_Lf[NOPS*NT];
__device__ float g_Lg[256*NT];
__device__ float g_Lh[256*NT];
__device__ float g_Lc[NT];
__device__ float g_Lb[NT];
__device__ float g_s1[NT], g_s2[NT];
__device__ double g_sabs[32];
__device__ double g_res[2];
__device__ __half g_W1h[NT*DFF*DM];   // [t][n(dff)][k(d)]
__device__ __half g_W2h[NT*DM*DFF];   // [t][n(d)][k(dff)]
__device__ double g_sumP[NT];
__device__ int g_fill[NT];
__device__ int g_nblocks;
__device__ float g_gate[BTOK];
__device__ int g_src[NT*TSTR];
__device__ int g_bmT[MAXBLK];
__device__ int g_bmR[MAXBLK];

// ---------------- helpers ----------------
__device__ __forceinline__ float tanh_fast(float v){
    float r; asm("tanh.approx.f32 %0, %1;" : "=f"(r) : "f"(v)); return r;
}
__device__ __forceinline__ uint32_t smem_u32(const void* p){
    uint32_t a;
    asm("{ .reg .u64 t; cvta.to.shared.u64 t, %1; cvt.u32.u64 %0, t; }":"=r"(a):"l"(p));
    return a;
}
__device__ __forceinline__ void ldsm4(uint32_t* r, uint32_t addr){
    asm volatile("ldmatrix.sync.aligned.m8n8.x4.shared.b16 {%0,%1,%2,%3}, [%4];"
        : "=r"(r[0]),"=r"(r[1]),"=r"(r[2]),"=r"(r[3]) : "r"(addr));
}
__device__ __forceinline__ void mma16(float* c, const uint32_t* a, const uint32_t* b){
    asm volatile("mma.sync.aligned.m16n8k16.row.col.f32.f16.f16.f32 "
        "{%0,%1,%2,%3},{%4,%5,%6,%7},{%8,%9},{%0,%1,%2,%3};"
        : "+f"(c[0]),"+f"(c[1]),"+f"(c[2]),"+f"(c[3])
        : "r"(a[0]),"r"(a[1]),"r"(a[2]),"r"(a[3]),"r"(b[0]),"r"(b[1]));
}
// fp16-accumulate mma, zero-init per call, promoted into fp32 regs
__device__ __forceinline__ void mma16h_acc(float* c, const uint32_t* a, const uint32_t* b){
    uint32_t d0, d1;
    asm volatile("mma.sync.aligned.m16n8k16.row.col.f16.f16.f16.f16 "
        "{%0,%1},{%2,%3,%4,%5},{%6,%7},{%8,%8};"
        : "=r"(d0),"=r"(d1)
        : "r"(a[0]),"r"(a[1]),"r"(a[2]),"r"(a[3]),"r"(b[0]),"r"(b[1]),"r"(0u));
    float2 f0 = __half22float2(*(__half2*)&d0);
    float2 f1 = __half22float2(*(__half2*)&d1);
    c[0]+=f0.x; c[1]+=f0.y; c[2]+=f1.x; c[3]+=f1.y;
}
__device__ __forceinline__ __half2 h2pack(float a, float b){
    return __floats2half2_rn(a, b);
}
__device__ __forceinline__ void cpa16(uint32_t dst, const void* src){
    asm volatile("cp.async.cg.shared.global [%0], [%1], 16;" :: "r"(dst),"l"(src):"memory");
}
__device__ __forceinline__ void cpa_commit(){
    asm volatile("cp.async.commit_group;":::"memory");
}
__device__ __forceinline__ void cpa_wait0(){
    asm volatile("cp.async.wait_group 0;":::"memory");
}

// ---------------- k_init ----------------
__global__ void k_init(){
    int i = threadIdx.x;
    if (i < NT){ g_sumP[i]=0.0; g_fill[i]=0; }
    if (i < 32) g_sabs[i]=0.0;
    if (i < 2)  g_res[i]=0.0;
}

// ---------------- k_tables ----------------
__global__ void k_tables(const float* __restrict__ oe, const float* __restrict__ Win){
    int gid = blockIdx.x*256 + threadIdx.x;
    if (gid < 32768){
        int av = gid >> 7, d = gid & 127;
        float s = 0.f;
        #pragma unroll
        for (int i=0;i<8;i++) if ((av>>i)&1) s += Win[(32+i)*DM + d];
        g_Tg[av*DM+d] = s;
    } else if (gid < 65536){
        int g2 = gid - 32768;
        int bv = g2 >> 7, d = g2 & 127;
        float s = 0.f;
        #pragma unroll
        for (int i=0;i<8;i++) if ((bv>>i)&1) s += Win[(40+i)*DM + d];
        g_Th[bv*DM+d] = s;
    } else if (gid < 66560){
        int g2 = gid - 65536;
        int op = g2 >> 7, d = g2 & 127;
        float s = 0.f;
        #pragma unroll
        for (int j=0;j<EMB;j++) s += oe[op*EMB+j]*Win[j*DM+d];
        g_Tf[op*DM+d] = s;
    }
}

// ---------------- k_lt ----------------
__global__ void k_lt(const float* __restrict__ Wr, const float* __restrict__ Win,
                     const float* __restrict__ bin){
    int gid = blockIdx.x*256+threadIdx.x;
    if (gid < 4096){
        int av=gid>>4, t=gid&15; float s=0.f;
        for(int d=0;d<DM;d++) s += g_Tg[av*DM+d]*Wr[d*NT+t];
        g_Lg[gid]=s;
    } else if (gid < 8192){
        int g2=gid-4096; int bv=g2>>4,t=g2&15; float s=0.f;
        for(int d=0;d<DM;d++) s += g_Th[bv*DM+d]*Wr[d*NT+t];
        g_Lh[g2]=s;
    } else if (gid < 8320){
        int g2=gid-8192; int op=g2>>4,t=g2&15; float s=0.f;
        for(int d=0;d<DM;d++) s += g_Tf[op*DM+d]*Wr[d*NT+t];
        g_Lf[g2]=s;
    } else if (gid < 8336){
        int t=gid-8320; float s=0.f;
        for(int d=0;d<DM;d++) s += Win[48*DM+d]*Wr[d*NT+t];
        g_Lc[t]=s;
    } else if (gid < 8352){
        int t=gid-8336; float s=0.f;
        for(int d=0;d<DM;d++) s += bin[d]*Wr[d*NT+t];
        g_Lb[t]=s;
    }
}

// ---------------- k_scalep ----------------
__global__ void k_scalep(const float* __restrict__ W1, const float* __restrict__ W2){
    __shared__ double red[256];
    int tile = blockIdx.x >> 4;
    int sub  = blockIdx.x & 15;
    const float* W = (tile < 16 ? W1 + tile*65536 : W2 + (tile-16)*65536) + sub*4096;
    const float4* W4 = (const float4*)W;
    double s = 0.0;
    #pragma unroll
    for (int r=0;r<4;r++){
        float4 v = W4[threadIdx.x + r*256];
        s += (double)(fabsf(v.x)+fabsf(v.y)+fabsf(v.z)+fabsf(v.w));
    }
    red[threadIdx.x]=s; __syncthreads();
    for (int o=128;o;o>>=1){ if(threadIdx.x<o) red[threadIdx.x]+=red[threadIdx.x+o]; __syncthreads(); }
    if (!threadIdx.x) atomicAdd(&g_sabs[tile], red[0]);
}

// ---------------- k_sfin ----------------
__global__ void k_sfin(){
    int t = threadIdx.x;
    if (t < 16) g_s1[t] = (float)(g_sabs[t]/65536.0);
    else if (t < 32) g_s2[t-16] = (float)(g_sabs[t]/65536.0);
}

// ---------------- k_quant: coalesced transpose via smem ----------------
// blocks 0..127: W1, tile t=b>>3, n0=(b&7)*64 ; region k[0,128) x n[n0,n0+64)
// blocks 128..255: W2, tile t, kk0=(b&7)*64 ; region kk[kk0,kk0+64) x nn[0,128)
__global__ void k_quant(const float* __restrict__ W1, const float* __restrict__ W2){
    __shared__ __half sh[64*130];
    __shared__ double red[256];
    int b = blockIdx.x, tid = threadIdx.x;
    double racc = 0.0;
    if (b < 128){
        int t = b>>3, n0 = (b&7)*64;
        float s = g_s1[t];
        const float* src = W1 + t*65536;
        #pragma unroll
        for (int j=0;j<32;j++){
            int i = tid + j*256;          // 8192 elems
            int k = i>>6, nx = i&63;
            float w = src[k*512 + n0 + nx];
            float aw = fabsf(w);
            bool nz = aw > 0.7f*s;
            float q = nz ? (w>0.f?1.f:-1.f) : 0.f;
            racc += (double)(nz ? fabsf(aw - s) : aw);
            sh[nx*130 + k] = __float2half(q);
        }
        __syncthreads();
        __half* dst = g_W1h + t*65536 + n0*128;
        #pragma unroll
        for (int j=0;j<32;j++){
            int i = tid + j*256;
            int n = i>>7, k = i&127;
            dst[n*128 + k] = sh[n*130 + k];
        }
        red[tid]=racc; __syncthreads();
        for(int o=128;o;o>>=1){ if(tid<o) red[tid]+=red[tid+o]; __syncthreads(); }
        if (!tid) atomicAdd(&g_res[0], red[0]);
    } else {
        int bb = b-128;
        int t = bb>>3, kk0 = (bb&7)*64;
        float s = g_s2[t];
        const float* src = W2 + t*65536;
        #pragma unroll
        for (int j=0;j<32;j++){
            int i = tid + j*256;
            int kk = i>>7, nn = i&127;
            float w = src[(kk0+kk)*128 + nn];
            float aw = fabsf(w);
            bool nz = aw > 0.7f*s;
            float q = nz ? (w>0.f?1.f:-1.f) : 0.f;
            racc += (double)(nz ? fabsf(aw - s) : aw);
            sh[kk*130 + nn] = __float2half(q);
        }
        __syncthreads();
        __half* dst = g_W2h + t*65536 + kk0;
        #pragma unroll
        for (int j=0;j<32;j++){
            int i = tid + j*256;
            int nn = i>>6, kx = i&63;
            dst[nn*512 + kx] = sh[kx*130 + nn];
        }
        red[tid]=racc; __syncthreads();
        for(int o=128;o;o>>=1){ if(tid<o) red[tid]+=red[tid+o]; __syncthreads(); }
        if (!tid) atomicAdd(&g_res[1], red[0]);
    }
}

// ---------------- k_route: logits, softmax, argmax, stats, fused scatter ----------------
__global__ void k_route(const int* __restrict__ op, const int* __restrict__ a,
                        const int* __restrict__ b, const int* __restrict__ c,
                        float* __restrict__ outIdx){
    __shared__ float sLf[NOPS*NT], sLg[256*NT], sLh[256*NT], sLc[NT], sLb[NT];
    __shared__ float sP[NT]; __shared__ int sC[NT]; __shared__ int sBase[NT];
    int tid = threadIdx.x;
    int lane = tid & 31;
    for (int i=tid;i<256*NT;i+=256){ sLg[i]=g_Lg[i]; sLh[i]=g_Lh[i]; }
    for (int i=tid;i<NOPS*NT;i+=256) sLf[i]=g_Lf[i];
    if (tid<NT){ sLc[tid]=g_Lc[tid]; sLb[tid]=g_Lb[tid]; sP[tid]=0.f; sC[tid]=0; }
    __syncthreads();
    int i = blockIdx.x*256+tid;
    int opv=op[i], av=a[i], bv=b[i]; float cv=(float)c[i];
    float l[NT]; float mx=-1e30f; int best=0;
    #pragma unroll
    for (int t=0;t<NT;t++){
        float v = sLf[opv*NT+t]+sLg[av*NT+t]+sLh[bv*NT+t]+cv*sLc[t]+sLb[t];
        l[t]=v;
        if (v>mx){mx=v;best=t;}
    }
    float den=0.f;
    #pragma unroll
    for (int t=0;t<NT;t++){ l[t]=__expf(l[t]-mx); den+=l[t]; }
    float inv = 1.f/den;
    #pragma unroll
    for (int t=0;t<NT;t++){
        float v = l[t]*inv;
        #pragma unroll
        for (int o=16;o;o>>=1) v += __shfl_xor_sync(0xffffffffu, v, o);
        if (lane==0) atomicAdd(&sP[t], v);
    }
    int rank = atomicAdd(&sC[best], 1);
    g_gate[i]=inv; outIdx[i]=(float)best;
    __syncthreads();
    if (tid<NT){
        sBase[tid] = atomicAdd(&g_fill[tid], sC[tid]);
        atomicAdd(&g_sumP[tid], (double)sP[tid]);
    }
    __syncthreads();
    g_src[best*TSTR + sBase[best] + rank] = i;
}

// ---------------- k_part (parallel fill) ----------------
__global__ void k_part(){
    __shared__ int pc[NT], po_[NT];
    int tid=threadIdx.x;
    if (tid<NT) pc[tid] = g_fill[tid];
    __syncthreads();
    if (tid==0){
        int nb=0;
        for (int t=0;t<NT;t++){ po_[t]=nb; nb += (pc[t]+MROWS-1)/MROWS; }
        g_nblocks = nb;
    }
    __syncthreads();
    for (int t=0;t<NT;t++){
        int bl = (pc[t]+MROWS-1)/MROWS;
        for (int bi=tid; bi<bl; bi+=256){ g_bmT[po_[t]+bi]=t; g_bmR[po_[t]+bi]=t*TSTR + bi*MROWS; }
        int cnt=pc[t]; int pad = bl*MROWS;
        for (int p=cnt+tid; p<pad; p+=256) g_src[t*TSTR+p] = -1;
    }
}

// ---------------- k_ffn: 256 threads, fp16-acc mma + ldmatrix + cp.async pipeline ----------------
__global__ void __launch_bounds__(256,1) k_ffn(
    const int* __restrict__ op, const int* __restrict__ aIn,
    const int* __restrict__ bIn, const int* __restrict__ cIn,
    const float* __restrict__ Win, const float* __restrict__ bin,
    const float* __restrict__ Wh1, const float* __restrict__ bh1,
    const float* __restrict__ Wh2, const float* __restrict__ bh2,
    float* __restrict__ outR)
{
    extern __shared__ __half sm[];
    __half* sX  = sm;
    __half* sW0 = sm + 128*SLDH;
    __half* sW1 = sm + 2*128*SLDH;
    __half* sG  = sm + 3*128*SLDH;
    __shared__ float sGate[MROWS];
    __shared__ int   sSrc[MROWS];
    __shared__ float sWh2[512], sbh1[64], sbh2[8];

    int bid = blockIdx.x;
    if (bid >= g_nblocks) return;
    int t  = g_bmT[bid], r0 = g_bmR[bid];
    int tid = threadIdx.x;
    int wid = tid>>5, lane = tid&31;
    int grp = lane>>2, tq = lane&3;
    int wm = wid&3, wn = wid>>2;            // 4 m-warps x 2 n-warps
    float s1 = g_s1[t], s2 = g_s2[t];

    uint32_t bX = smem_u32(sX), bG = smem_u32(sG);
    uint32_t bufs[2] = { smem_u32(sW0), smem_u32(sW1) };
    uint32_t aoff  = (uint32_t)((lane&15)*SLDH + (lane>>4)*8)*2;
    uint32_t boff4 = (uint32_t)(((lane&7) + ((lane>>4)<<3))*SLDH + ((lane>>3)&1)*8)*2;

    const __half* W1p = g_W1h + t*65536;
    const __half* W2p = g_W2h + t*65536;

    // ---- prefetch stage 0 (W1 chunk 0) ----
    {
        #pragma unroll
        for (int j=0;j<8;j++){
            int i = tid + j*256;
            int row = i>>4, ck = i&15;
            cpa16(bufs[0] + (uint32_t)(row*SLDH + ck*8)*2, W1p + row*128 + ck*8);
        }
        cpa_commit();
    }

    // ---- build X tile (fp16); 2 threads/row ----
    {
        int row = tid>>1, half = tid&1;
        int token = g_src[r0+row];
        if (half==0){ sSrc[row]=token; sGate[row]=(token>=0)?g_gate[token]:0.f; }
        const float* wc = Win + 48*DM;
        __half* dst = sX + row*SLDH + half*64;
        if (token>=0){
            int opv=op[token], av=aIn[token], bv=bIn[token]; float cv=(float)cIn[token];
            const float* tf=&g_Tf[opv*DM+half*64]; const float* tg=&g_Tg[av*DM+half*64];
            const float* th=&g_Th[bv*DM+half*64];
            const float* wcc=wc+half*64; const float* bb=bin+half*64;
            #pragma unroll 8
            for (int d=0; d<64; d+=2){
                float x0 = tf[d]+tg[d]+th[d]+cv*wcc[d]+bb[d];
                float x1 = tf[d+1]+tg[d+1]+th[d+1]+cv*wcc[d+1]+bb[d+1];
                *(__half2*)(dst+d) = h2pack(x0,x1);
            }
        } else {
            #pragma unroll 8
            for (int d=0; d<64; d+=2) *(uint32_t*)(dst+d) = 0u;
        }
    }
    for (int i=tid;i<512;i+=256) sWh2[i]=Wh2[i];
    if (tid<64) sbh1[tid]=bh1[tid];
    if (tid<8)  sbh2[tid]=bh2[tid];

    float c2[2][8][4];
    #pragma unroll
    for(int mt=0;mt<2;mt++)
        #pragma unroll
        for(int nt=0;nt<8;nt++)
            #pragma unroll
            for(int e=0;e<4;e++) c2[mt][nt][e]=0.f;

    cpa_wait0();
    __syncthreads();

    for (int s=0;s<8;s++){
        if (s<7){
            int sn = s+1, ch = sn>>1;
            uint32_t dstb = bufs[sn&1];
            if (!(sn&1)){
                const __half* src = W1p + ch*16384;
                #pragma unroll
                for (int j=0;j<8;j++){
                    int i = tid + j*256;
                    int row = i>>4, ck = i&15;
                    cpa16(dstb + (uint32_t)(row*SLDH + ck*8)*2, src + row*128 + ck*8);
                }
            } else {
                const __half* src = W2p + ch*128;
                #pragma unroll
                for (int j=0;j<8;j++){
                    int i = tid + j*256;
                    int row = i>>4, ck = i&15;
                    cpa16(dstb + (uint32_t)(row*SLDH + ck*8)*2, src + row*512 + ck*8);
                }
            }
            cpa_commit();
        }
        uint32_t bw = bufs[s&1];
        if (!(s&1)){
            float c1[2][8][4];
            #pragma unroll
            for(int mt=0;mt<2;mt++)
                #pragma unroll
                for(int nt=0;nt<8;nt++)
                    #pragma unroll
                    for(int e=0;e<4;e++) c1[mt][nt][e]=0.f;
            #pragma unroll
            for (int kk=0;kk<8;kk++){
                uint32_t af[2][4];
                ldsm4(af[0], bX + aoff + (uint32_t)((wm*32)*SLDH + kk*16)*2);
                ldsm4(af[1], bX + aoff + (uint32_t)((wm*32+16)*SLDH + kk*16)*2);
                #pragma unroll
                for (int ntp=0;ntp<4;ntp++){
                    uint32_t bq[4];
                    ldsm4(bq, bw + boff4 + (uint32_t)((wn*64+ntp*16)*SLDH + kk*16)*2);
                    mma16h_acc(c1[0][2*ntp],   af[0], bq);
                    mma16h_acc(c1[1][2*ntp],   af[1], bq);
                    mma16h_acc(c1[0][2*ntp+1], af[0], bq+2);
                    mma16h_acc(c1[1][2*ntp+1], af[1], bq+2);
                }
            }
            #pragma unroll
            for (int mt=0;mt<2;mt++){
                int row0 = wm*32+mt*16+grp;
                #pragma unroll
                for (int nt=0;nt<8;nt++){
                    int col = wn*64+nt*8+2*tq;
                    float v0=s1*c1[mt][nt][0], v1=s1*c1[mt][nt][1];
                    float v2=s1*c1[mt][nt][2], v3=s1*c1[mt][nt][3];
                    float g0 = 0.5f*v0*(1.f+tanh_fast(0.7978845608f*(v0+0.044715f*v0*v0*v0)));
                    float g1 = 0.5f*v1*(1.f+tanh_fast(0.7978845608f*(v1+0.044715f*v1*v1*v1)));
                    float g2 = 0.5f*v2*(1.f+tanh_fast(0.7978845608f*(v2+0.044715f*v2*v2*v2)));
                    float g3 = 0.5f*v3*(1.f+tanh_fast(0.7978845608f*(v3+0.044715f*v3*v3*v3)));
                    *(__half2*)(sG + row0*SLDH + col)     = h2pack(g0,g1);
                    *(__half2*)(sG + (row0+8)*SLDH + col) = h2pack(g2,g3);
                }
            }
        } else {
            #pragma unroll
            for (int kk=0;kk<8;kk++){
                uint32_t af[2][4];
                ldsm4(af[0], bG + aoff + (uint32_t)((wm*32)*SLDH + kk*16)*2);
                ldsm4(af[1], bG + aoff + (uint32_t)((wm*32+16)*SLDH + kk*16)*2);
                #pragma unroll
                for (int ntp=0;ntp<4;ntp++){
                    uint32_t bq[4];
                    ldsm4(bq, bw + boff4 + (uint32_t)((wn*64+ntp*16)*SLDH + kk*16)*2);
                    mma16h_acc(c2[0][2*ntp],   af[0], bq);
                    mma16h_acc(c2[1][2*ntp],   af[1], bq);
                    mma16h_acc(c2[0][2*ntp+1], af[0], bq+2);
                    mma16h_acc(c2[1][2*ntp+1], af[1], bq+2);
                }
            }
        }
        cpa_wait0();
        __syncthreads();
    }

    // ---- gated output -> sX (head A, fp16) ----
    #pragma unroll
    for (int mt=0;mt<2;mt++){
        int row0 = wm*32+mt*16+grp;
        float ga = sGate[row0], gb = sGate[row0+8];
        #pragma unroll
        for (int nt=0;nt<8;nt++){
            int col = wn*64+nt*8+2*tq;
            *(__half2*)(sX + row0*SLDH + col)     = h2pack(s2*c2[mt][nt][0]*ga, s2*c2[mt][nt][1]*ga);
            *(__half2*)(sX + (row0+8)*SLDH + col) = h2pack(s2*c2[mt][nt][2]*gb, s2*c2[mt][nt][3]*gb);
        }
    }
    // ---- Wh1^T -> sW0 [64 n][128 k] ----
    for (int i=tid; i<64*64; i+=256){
        int n = i>>6, k = (i&63)*2;
        *(__half2*)(sW0 + n*SLDH + k) = h2pack(Wh1[k*64+n], Wh1[(k+1)*64+n]);
    }
    __syncthreads();
    // ---- head GEMM: [128x128] @ [64x128]^T (fp32 accum) ----
    uint32_t bw0 = bufs[0];
    float c3[2][4][4];
    #pragma unroll
    for(int mt=0;mt<2;mt++)
        #pragma unroll
        for(int nt=0;nt<4;nt++)
            #pragma unroll
            for(int e=0;e<4;e++) c3[mt][nt][e]=0.f;
    #pragma unroll
    for (int kk=0;kk<8;kk++){
        uint32_t af[2][4];
        ldsm4(af[0], bX + aoff + (uint32_t)((wm*32)*SLDH + kk*16)*2);
        ldsm4(af[1], bX + aoff + (uint32_t)((wm*32+16)*SLDH + kk*16)*2);
        #pragma unroll
        for (int ntp=0;ntp<2;ntp++){
            uint32_t bq[4];
            ldsm4(bq, bw0 + boff4 + (uint32_t)((wn*32+ntp*16)*SLDH + kk*16)*2);
            mma16(c3[0][2*ntp],   af[0], bq);
            mma16(c3[1][2*ntp],   af[1], bq);
            mma16(c3[0][2*ntp+1], af[0], bq+2);
            mma16(c3[1][2*ntp+1], af[1], bq+2);
        }
    }
    __syncthreads();
    // ---- h = relu(c3+bh1) -> float buffer (reuse sX) ----
    float* sH = (float*)sX;   // [128][66]
    #pragma unroll
    for (int mt=0;mt<2;mt++){
        int row0 = wm*32+mt*16+grp;
        #pragma unroll
        for (int nt=0;nt<4;nt++){
            int col = wn*32+nt*8+2*tq;
            sH[row0*66+col]       = fmaxf(c3[mt][nt][0]+sbh1[col],   0.f);
            sH[row0*66+col+1]     = fmaxf(c3[mt][nt][1]+sbh1[col+1], 0.f);
            sH[(row0+8)*66+col]   = fmaxf(c3[mt][nt][2]+sbh1[col],   0.f);
            sH[(row0+8)*66+col+1] = fmaxf(c3[mt][nt][3]+sbh1[col+1], 0.f);
        }
    }
    __syncthreads();
    // ---- final 64->8 + sigmoid (2 threads/row) ----
    {
        int row = tid>>1, c0 = (tid&1)*4;
        int token = sSrc[row];
        if (token>=0){
            float acc0=sbh2[c0], acc1=sbh2[c0+1], acc2=sbh2[c0+2], acc3=sbh2[c0+3];
            #pragma unroll 8
            for (int k2=0;k2<64;k2++){
                float hv = sH[row*66+k2];
                acc0 += hv*sWh2[k2*8+c0];
                acc1 += hv*sWh2[k2*8+c0+1];
                acc2 += hv*sWh2[k2*8+c0+2];
                acc3 += hv*sWh2[k2*8+c0+3];
            }
            float* o = outR + (size_t)token*8 + c0;
            o[0] = 1.f/(1.f+__expf(-acc0));
            o[1] = 1.f/(1.f+__expf(-acc1));
            o[2] = 1.f/(1.f+__expf(-acc2));
            o[3] = 1.f/(1.f+__expf(-acc3));
        }
    }
}

// ---------------- k_aux ----------------
__global__ void k_aux(float* __restrict__ aux){
    if (threadIdx.x==0){
        double sp=0.0, cp[4]={0,0,0,0};
        for (int t=0;t<NT;t++){
            double frac = (double)g_fill[t]/(double)BTOK;
            double mp = g_sumP[t]/(double)BTOK;
            sp += frac*mp;
            cp[t>>2] += mp;
        }
        double sparsity = 16.0*sp;
        double tern = g_res[0]/1048576.0 + g_res[1]/1048576.0;
        double divv = 0.0;
        for (int i=0;i<4;i++) divv += cp[i]*log(cp[i]+1e-9);
        aux[0] = (float)(0.01*tern + 0.005*sparsity + 0.01*divv);
    }
}

// ---------------- launch ----------------
extern "C" void kernel_launch(void* const* d_in, const int* in_sizes, int n_in,
                              void* d_out, int out_size){
    const int *op=nullptr,*a=nullptr,*b=nullptr,*c=nullptr;
    const float *oe=nullptr,*Win=nullptr,*bin=nullptr,*Wr=nullptr,*W1=nullptr,*W2=nullptr;
    const float *Wh1=nullptr,*bh1=nullptr,*Wh2=nullptr,*bh2=nullptr;
    int nb_=0, nw=0;
    for (int i=0;i<n_in;i++){
        int s = in_sizes[i]; void* p = (void*)d_in[i];
        switch(s){
            case BTOK:
                if(nb_==0) op=(const int*)p; else if(nb_==1) a=(const int*)p;
                else if(nb_==2) b=(const int*)p; else c=(const int*)p;
                nb_++; break;
            case 256:  oe=(const float*)p; break;
            case 6272: Win=(const float*)p; break;
            case 128:  bin=(const float*)p; break;
            case 2048: Wr=(const float*)p; break;
            case 1048576: if(nw==0) W1=(const float*)p; else W2=(const float*)p; nw++; break;
            case 8192: Wh1=(const float*)p; break;
            case 64:   bh1=(const float*)p; break;
            case 512:  Wh2=(const float*)p; break;
            case 8:    bh2=(const float*)p; break;
            default: break;
        }
    }
    float* out = (float*)d_out;
    int smem = 4*128*SLDH*2;
    cudaFuncSetAttribute(k_ffn, cudaFuncAttributeMaxDynamicSharedMemorySize, smem);

    k_init<<<1,32>>>();
    k_tables<<<260,256>>>(oe,Win);
    k_lt<<<33,256>>>(Wr,Win,bin);
    k_scalep<<<512,256>>>(W1,W2);
    k_sfin<<<1,32>>>();
    k_quant<<<256,256>>>(W1,W2);
    k_route<<<BTOK/256,256>>>(op,a,b,c,out + (size_t)BTOK*8);
    k_part<<<1,256>>>();
    k_ffn<<<MAXBLK,256,smem>>>(op,a,b,c,Win,bin,Wh1,bh1,Wh2,bh2,out);
    k_aux<<<1,32>>>(out + (size_t)BTOK*9);
}

// round 10
// speedup vs baseline: 1.3954x; 1.3951x over previous
#include <cuda_runtime.h>
#include <cuda_fp16.h>
#include <cstdint>

#define BTOK 262144
#define DM 128
#define DFF 512
#define NT 16
#define NOPS 8
#define EMB 32
#define MROWS 128
#define SLDH 136
#define MAXBLK (BTOK/MROWS + NT)
#define TSTR (BTOK + 128)

// ---------------- device scratch ----------------
__device__ float g_Tf[NOPS*DM];
__device__ float g_Tg[256*DM];
__device__ float g_Th[256*DM];
__device__ float g_Lf[NOPS*NT];
__device__ float g_Lg[256*NT];
__device__ float g_Lh[256*NT];
__device__ float g_Lc[NT];
__device__ float g_Lb[NT];
__device__ float g_s1[NT], g_s2[NT];
__device__ double g_sabs[32];
__device__ double g_res[2];
__device__ __half g_W1h[NT*DFF*DM];   // [t][n(dff)][k(d)]
__device__ __half g_W2h[NT*DM*DFF];   // [t][nn(d)][kk(dff)]
__device__ __half g_Wch[NT*64*DFF];   // [t][n(64)][k(dff)] = s2 * W2q @ Wh1, transposed
__device__ double g_sumP[NT];
__device__ int g_fill[NT];
__device__ int g_nblocks;
__device__ float g_gate[BTOK];
__device__ int g_src[NT*TSTR];
__device__ int g_bmT[MAXBLK];
__device__ int g_bmR[MAXBLK];

// ---------------- helpers ----------------
__device__ __forceinline__ float tanh_fast(float v){
    float r; asm("tanh.approx.f32 %0, %1;" : "=f"(r) : "f"(v)); return r;
}
__device__ __forceinline__ uint32_t smem_u32(const void* p){
    uint32_t a;
    asm("{ .reg .u64 t; cvta.to.shared.u64 t, %1; cvt.u32.u64 %0, t; }":"=r"(a):"l"(p));
    return a;
}
__device__ __forceinline__ void ldsm4(uint32_t* r, uint32_t addr){
    asm volatile("ldmatrix.sync.aligned.m8n8.x4.shared.b16 {%0,%1,%2,%3}, [%4];"
        : "=r"(r[0]),"=r"(r[1]),"=r"(r[2]),"=r"(r[3]) : "r"(addr));
}
__device__ __forceinline__ void mma16(float* c, const uint32_t* a, const uint32_t* b){
    asm volatile("mma.sync.aligned.m16n8k16.row.col.f32.f16.f16.f32 "
        "{%0,%1,%2,%3},{%4,%5,%6,%7},{%8,%9},{%0,%1,%2,%3};"
        : "+f"(c[0]),"+f"(c[1]),"+f"(c[2]),"+f"(c[3])
        : "r"(a[0]),"r"(a[1]),"r"(a[2]),"r"(a[3]),"r"(b[0]),"r"(b[1]));
}
__device__ __forceinline__ __half2 h2pack(float a, float b){
    return __floats2half2_rn(a, b);
}
__device__ __forceinline__ void cpa16(uint32_t dst, const void* src){
    asm volatile("cp.async.cg.shared.global [%0], [%1], 16;" :: "r"(dst),"l"(src):"memory");
}
__device__ __forceinline__ void cpa_commit(){
    asm volatile("cp.async.commit_group;":::"memory");
}
__device__ __forceinline__ void cpa_wait0(){
    asm volatile("cp.async.wait_group 0;":::"memory");
}

// ---------------- k_init ----------------
__global__ void k_init(){
    int i = threadIdx.x;
    if (i < NT){ g_sumP[i]=0.0; g_fill[i]=0; }
    if (i < 32) g_sabs[i]=0.0;
    if (i < 2)  g_res[i]=0.0;
}

// ---------------- k_tables ----------------
__global__ void k_tables(const float* __restrict__ oe, const float* __restrict__ Win){
    int gid = blockIdx.x*256 + threadIdx.x;
    if (gid < 32768){
        int av = gid >> 7, d = gid & 127;
        float s = 0.f;
        #pragma unroll
        for (int i=0;i<8;i++) if ((av>>i)&1) s += Win[(32+i)*DM + d];
        g_Tg[av*DM+d] = s;
    } else if (gid < 65536){
        int g2 = gid - 32768;
        int bv = g2 >> 7, d = g2 & 127;
        float s = 0.f;
        #pragma unroll
        for (int i=0;i<8;i++) if ((bv>>i)&1) s += Win[(40+i)*DM + d];
        g_Th[bv*DM+d] = s;
    } else if (gid < 66560){
        int g2 = gid - 65536;
        int op = g2 >> 7, d = g2 & 127;
        float s = 0.f;
        #pragma unroll
        for (int j=0;j<EMB;j++) s += oe[op*EMB+j]*Win[j*DM+d];
        g_Tf[op*DM+d] = s;
    }
}

// ---------------- k_lt ----------------
__global__ void k_lt(const float* __restrict__ Wr, const float* __restrict__ Win,
                     const float* __restrict__ bin){
    int gid = blockIdx.x*256+threadIdx.x;
    if (gid < 4096){
        int av=gid>>4, t=gid&15; float s=0.f;
        for(int d=0;d<DM;d++) s += g_Tg[av*DM+d]*Wr[d*NT+t];
        g_Lg[gid]=s;
    } else if (gid < 8192){
        int g2=gid-4096; int bv=g2>>4,t=g2&15; float s=0.f;
        for(int d=0;d<DM;d++) s += g_Th[bv*DM+d]*Wr[d*NT+t];
        g_Lh[g2]=s;
    } else if (gid < 8320){
        int g2=gid-8192; int op=g2>>4,t=g2&15; float s=0.f;
        for(int d=0;d<DM;d++) s += g_Tf[op*DM+d]*Wr[d*NT+t];
        g_Lf[g2]=s;
    } else if (gid < 8336){
        int t=gid-8320; float s=0.f;
        for(int d=0;d<DM;d++) s += Win[48*DM+d]*Wr[d*NT+t];
        g_Lc[t]=s;
    } else if (gid < 8352){
        int t=gid-8336; float s=0.f;
        for(int d=0;d<DM;d++) s += bin[d]*Wr[d*NT+t];
        g_Lb[t]=s;
    }
}

// ---------------- k_scalep ----------------
__global__ void k_scalep(const float* __restrict__ W1, const float* __restrict__ W2){
    __shared__ double red[256];
    int tile = blockIdx.x >> 4;
    int sub  = blockIdx.x & 15;
    const float* W = (tile < 16 ? W1 + tile*65536 : W2 + (tile-16)*65536) + sub*4096;
    const float4* W4 = (const float4*)W;
    double s = 0.0;
    #pragma unroll
    for (int r=0;r<4;r++){
        float4 v = W4[threadIdx.x + r*256];
        s += (double)(fabsf(v.x)+fabsf(v.y)+fabsf(v.z)+fabsf(v.w));
    }
    red[threadIdx.x]=s; __syncthreads();
    for (int o=128;o;o>>=1){ if(threadIdx.x<o) red[threadIdx.x]+=red[threadIdx.x+o]; __syncthreads(); }
    if (!threadIdx.x) atomicAdd(&g_sabs[tile], red[0]);
}

// ---------------- k_sfin ----------------
__global__ void k_sfin(){
    int t = threadIdx.x;
    if (t < 16) g_s1[t] = (float)(g_sabs[t]/65536.0);
    else if (t < 32) g_s2[t-16] = (float)(g_sabs[t]/65536.0);
}

// ---------------- k_quant: coalesced transpose via smem ----------------
__global__ void k_quant(const float* __restrict__ W1, const float* __restrict__ W2){
    __shared__ __half sh[64*130];
    __shared__ double red[256];
    int b = blockIdx.x, tid = threadIdx.x;
    double racc = 0.0;
    if (b < 128){
        int t = b>>3, n0 = (b&7)*64;
        float s = g_s1[t];
        const float* src = W1 + t*65536;
        #pragma unroll
        for (int j=0;j<32;j++){
            int i = tid + j*256;
            int k = i>>6, nx = i&63;
            float w = src[k*512 + n0 + nx];
            float aw = fabsf(w);
            bool nz = aw > 0.7f*s;
            float q = nz ? (w>0.f?1.f:-1.f) : 0.f;
            racc += (double)(nz ? fabsf(aw - s) : aw);
            sh[nx*130 + k] = __float2half(q);
        }
        __syncthreads();
        __half* dst = g_W1h + t*65536 + n0*128;
        #pragma unroll
        for (int j=0;j<32;j++){
            int i = tid + j*256;
            int n = i>>7, k = i&127;
            dst[n*128 + k] = sh[n*130 + k];
        }
        red[tid]=racc; __syncthreads();
        for(int o=128;o;o>>=1){ if(tid<o) red[tid]+=red[tid+o]; __syncthreads(); }
        if (!tid) atomicAdd(&g_res[0], red[0]);
    } else {
        int bb = b-128;
        int t = bb>>3, kk0 = (bb&7)*64;
        float s = g_s2[t];
        const float* src = W2 + t*65536;
        #pragma unroll
        for (int j=0;j<32;j++){
            int i = tid + j*256;
            int kk = i>>7, nn = i&127;
            float w = src[(kk0+kk)*128 + nn];
            float aw = fabsf(w);
            bool nz = aw > 0.7f*s;
            float q = nz ? (w>0.f?1.f:-1.f) : 0.f;
            racc += (double)(nz ? fabsf(aw - s) : aw);
            sh[kk*130 + nn] = __float2half(q);
        }
        __syncthreads();
        __half* dst = g_W2h + t*65536 + kk0;
        #pragma unroll
        for (int j=0;j<32;j++){
            int i = tid + j*256;
            int nn = i>>6, kx = i&63;
            dst[nn*512 + kx] = sh[kx*130 + nn];
        }
        red[tid]=racc; __syncthreads();
        for(int o=128;o;o>>=1){ if(tid<o) red[tid]+=red[tid+o]; __syncthreads(); }
        if (!tid) atomicAdd(&g_res[1], red[0]);
    }
}

// ---------------- k_wc: Wc[t][n][k] = s2 * sum_d W2q[t][d][k] * Wh1[d][n] ----------------
// blocks: t = b>>4, k0 = (b&15)*32
__global__ void k_wc(const float* __restrict__ Wh1){
    __shared__ float sWh1[128*64];     // [d][n]
    __shared__ __half sW2[128*32];     // [d][kx]
    int b = blockIdx.x, tid = threadIdx.x;
    int t = b>>4, k0 = (b&15)*32;
    float s2 = g_s2[t];
    #pragma unroll
    for (int j=0;j<32;j++) sWh1[tid + j*256] = Wh1[tid + j*256];
    const __half* W2p = g_W2h + t*65536 + k0;
    #pragma unroll
    for (int j=0;j<16;j++){
        int i = tid + j*256;
        int d = i>>5, kx = i&31;
        sW2[d*32 + kx] = W2p[d*512 + kx];
    }
    __syncthreads();
    #pragma unroll
    for (int j=0;j<8;j++){
        int o = tid + j*256;           // 2048 outputs: n(64) fast, kx(32)
        int n = o&63, kx = o>>6;
        float acc = 0.f;
        #pragma unroll 8
        for (int d=0; d<128; d++)
            acc += __half2float(sW2[d*32 + kx]) * sWh1[d*64 + n];
        g_Wch[t*32768 + n*512 + k0 + kx] = __float2half(s2*acc);
    }
}

// ---------------- k_route: logits, softmax, argmax, stats, fused scatter ----------------
__global__ void k_route(const int* __restrict__ op, const int* __restrict__ a,
                        const int* __restrict__ b, const int* __restrict__ c,
                        float* __restrict__ outIdx){
    __shared__ float sLf[NOPS*NT], sLg[256*NT], sLh[256*NT], sLc[NT], sLb[NT];
    __shared__ float sP[NT]; __shared__ int sC[NT]; __shared__ int sBase[NT];
    int tid = threadIdx.x;
    int lane = tid & 31;
    for (int i=tid;i<256*NT;i+=256){ sLg[i]=g_Lg[i]; sLh[i]=g_Lh[i]; }
    for (int i=tid;i<NOPS*NT;i+=256) sLf[i]=g_Lf[i];
    if (tid<NT){ sLc[tid]=g_Lc[tid]; sLb[tid]=g_Lb[tid]; sP[tid]=0.f; sC[tid]=0; }
    __syncthreads();
    int i = blockIdx.x*256+tid;
    int opv=op[i], av=a[i], bv=b[i]; float cv=(float)c[i];
    float l[NT]; float mx=-1e30f; int best=0;
    #pragma unroll
    for (int t=0;t<NT;t++){
        float v = sLf[opv*NT+t]+sLg[av*NT+t]+sLh[bv*NT+t]+cv*sLc[t]+sLb[t];
        l[t]=v;
        if (v>mx){mx=v;best=t;}
    }
    float den=0.f;
    #pragma unroll
    for (int t=0;t<NT;t++){ l[t]=__expf(l[t]-mx); den+=l[t]; }
    float inv = 1.f/den;
    #pragma unroll
    for (int t=0;t<NT;t++){
        float v = l[t]*inv;
        #pragma unroll
        for (int o=16;o;o>>=1) v += __shfl_xor_sync(0xffffffffu, v, o);
        if (lane==0) atomicAdd(&sP[t], v);
    }
    int rank = atomicAdd(&sC[best], 1);
    g_gate[i]=inv; outIdx[i]=(float)best;
    __syncthreads();
    if (tid<NT){
        sBase[tid] = atomicAdd(&g_fill[tid], sC[tid]);
        atomicAdd(&g_sumP[tid], (double)sP[tid]);
    }
    __syncthreads();
    g_src[best*TSTR + sBase[best] + rank] = i;
}

// ---------------- k_part (parallel fill) ----------------
__global__ void k_part(){
    __shared__ int pc[NT], po_[NT];
    int tid=threadIdx.x;
    if (tid<NT) pc[tid] = g_fill[tid];
    __syncthreads();
    if (tid==0){
        int nb=0;
        for (int t=0;t<NT;t++){ po_[t]=nb; nb += (pc[t]+MROWS-1)/MROWS; }
        g_nblocks = nb;
    }
    __syncthreads();
    for (int t=0;t<NT;t++){
        int bl = (pc[t]+MROWS-1)/MROWS;
        for (int bi=tid; bi<bl; bi+=256){ g_bmT[po_[t]+bi]=t; g_bmR[po_[t]+bi]=t*TSTR + bi*MROWS; }
        int cnt=pc[t]; int pad = bl*MROWS;
        for (int p=cnt+tid; p<pad; p+=256) g_src[t*TSTR+p] = -1;
    }
}

// ---------------- k_ffn: 256 threads, fused GEMM2+head via Wc ----------------
__global__ void __launch_bounds__(256,1) k_ffn(
    const int* __restrict__ op, const int* __restrict__ aIn,
    const int* __restrict__ bIn, const int* __restrict__ cIn,
    const float* __restrict__ Win, const float* __restrict__ bin,
    const float* __restrict__ bh1,
    const float* __restrict__ Wh2, const float* __restrict__ bh2,
    float* __restrict__ outR)
{
    extern __shared__ __half sm[];
    __half* sX  = sm;
    __half* sW0 = sm + 128*SLDH;
    __half* sW1 = sm + 2*128*SLDH;
    __half* sG  = sm + 3*128*SLDH;
    __shared__ float sGate[MROWS];
    __shared__ int   sSrc[MROWS];
    __shared__ float sWh2[512], sbh1[64], sbh2[8];

    int bid = blockIdx.x;
    if (bid >= g_nblocks) return;
    int t  = g_bmT[bid], r0 = g_bmR[bid];
    int tid = threadIdx.x;
    int wid = tid>>5, lane = tid&31;
    int grp = lane>>2, tq = lane&3;
    int wm = wid&3, wn = wid>>2;            // 4 m-warps x 2 n-warps
    float s1 = g_s1[t];

    uint32_t bX = smem_u32(sX), bG = smem_u32(sG);
    uint32_t bufs[2] = { smem_u32(sW0), smem_u32(sW1) };
    uint32_t aoff  = (uint32_t)((lane&15)*SLDH + (lane>>4)*8)*2;
    uint32_t boff4 = (uint32_t)(((lane&7) + ((lane>>4)<<3))*SLDH + ((lane>>3)&1)*8)*2;

    const __half* W1p = g_W1h + t*65536;
    const __half* Wcp = g_Wch + t*32768;

    // ---- prefetch stage 0 (W1 chunk 0) ----
    {
        #pragma unroll
        for (int j=0;j<8;j++){
            int i = tid + j*256;
            int row = i>>4, ck = i&15;
            cpa16(bufs[0] + (uint32_t)(row*SLDH + ck*8)*2, W1p + row*128 + ck*8);
        }
        cpa_commit();
    }

    // ---- build X tile (fp16); 2 threads/row ----
    {
        int row = tid>>1, half = tid&1;
        int token = g_src[r0+row];
        if (half==0){ sSrc[row]=token; sGate[row]=(token>=0)?g_gate[token]:0.f; }
        const float* wc = Win + 48*DM;
        __half* dst = sX + row*SLDH + half*64;
        if (token>=0){
            int opv=op[token], av=aIn[token], bv=bIn[token]; float cv=(float)cIn[token];
            const float* tf=&g_Tf[opv*DM+half*64]; const float* tg=&g_Tg[av*DM+half*64];
            const float* th=&g_Th[bv*DM+half*64];
            const float* wcc=wc+half*64; const float* bb=bin+half*64;
            #pragma unroll 8
            for (int d=0; d<64; d+=2){
                float x0 = tf[d]+tg[d]+th[d]+cv*wcc[d]+bb[d];
                float x1 = tf[d+1]+tg[d+1]+th[d+1]+cv*wcc[d+1]+bb[d+1];
                *(__half2*)(dst+d) = h2pack(x0,x1);
            }
        } else {
            #pragma unroll 8
            for (int d=0; d<64; d+=2) *(uint32_t*)(dst+d) = 0u;
        }
    }
    for (int i=tid;i<512;i+=256) sWh2[i]=Wh2[i];
    if (tid<64) sbh1[tid]=bh1[tid];
    if (tid<8)  sbh2[tid]=bh2[tid];

    float c2[2][4][4];
    #pragma unroll
    for(int mt=0;mt<2;mt++)
        #pragma unroll
        for(int nt=0;nt<4;nt++)
            #pragma unroll
            for(int e=0;e<4;e++) c2[mt][nt][e]=0.f;

    cpa_wait0();
    __syncthreads();

    for (int s=0;s<8;s++){
        if (s<7){
            int sn = s+1, ch = sn>>1;
            uint32_t dstb = bufs[sn&1];
            if (!(sn&1)){
                const __half* src = W1p + ch*16384;
                #pragma unroll
                for (int j=0;j<8;j++){
                    int i = tid + j*256;
                    int row = i>>4, ck = i&15;
                    cpa16(dstb + (uint32_t)(row*SLDH + ck*8)*2, src + row*128 + ck*8);
                }
            } else {
                const __half* src = Wcp + ch*128;
                #pragma unroll
                for (int j=0;j<4;j++){
                    int i = tid + j*256;
                    int row = i>>4, ck = i&15;
                    cpa16(dstb + (uint32_t)(row*SLDH + ck*8)*2, src + row*512 + ck*8);
                }
            }
            cpa_commit();
        }
        uint32_t bw = bufs[s&1];
        if (!(s&1)){
            // ---- GEMM1: X @ W1[ch] -> c1; gelu -> sG ----
            float c1[2][8][4];
            #pragma unroll
            for(int mt=0;mt<2;mt++)
                #pragma unroll
                for(int nt=0;nt<8;nt++)
                    #pragma unroll
                    for(int e=0;e<4;e++) c1[mt][nt][e]=0.f;
            #pragma unroll
            for (int kk=0;kk<8;kk++){
                uint32_t af[2][4];
                ldsm4(af[0], bX + aoff + (uint32_t)((wm*32)*SLDH + kk*16)*2);
                ldsm4(af[1], bX + aoff + (uint32_t)((wm*32+16)*SLDH + kk*16)*2);
                #pragma unroll
                for (int ntp=0;ntp<4;ntp++){
                    uint32_t bq[4];
                    ldsm4(bq, bw + boff4 + (uint32_t)((wn*64+ntp*16)*SLDH + kk*16)*2);
                    mma16(c1[0][2*ntp],   af[0], bq);
                    mma16(c1[1][2*ntp],   af[1], bq);
                    mma16(c1[0][2*ntp+1], af[0], bq+2);
                    mma16(c1[1][2*ntp+1], af[1], bq+2);
                }
            }
            #pragma unroll
            for (int mt=0;mt<2;mt++){
                int row0 = wm*32+mt*16+grp;
                #pragma unroll
                for (int nt=0;nt<8;nt++){
                    int col = wn*64+nt*8+2*tq;
                    float v0=s1*c1[mt][nt][0], v1=s1*c1[mt][nt][1];
                    float v2=s1*c1[mt][nt][2], v3=s1*c1[mt][nt][3];
                    float g0 = 0.5f*v0*(1.f+tanh_fast(0.7978845608f*(v0+0.044715f*v0*v0*v0)));
                    float g1 = 0.5f*v1*(1.f+tanh_fast(0.7978845608f*(v1+0.044715f*v1*v1*v1)));
                    float g2 = 0.5f*v2*(1.f+tanh_fast(0.7978845608f*(v2+0.044715f*v2*v2*v2)));
                    float g3 = 0.5f*v3*(1.f+tanh_fast(0.7978845608f*(v3+0.044715f*v3*v3*v3)));
                    *(__half2*)(sG + row0*SLDH + col)     = h2pack(g0,g1);
                    *(__half2*)(sG + (row0+8)*SLDH + col) = h2pack(g2,g3);
                }
            }
        } else {
            // ---- fused GEMM2+head: sG @ Wc[ch] accumulate into c2 (N=64) ----
            #pragma unroll
            for (int kk=0;kk<8;kk++){
                uint32_t af[2][4];
                ldsm4(af[0], bG + aoff + (uint32_t)((wm*32)*SLDH + kk*16)*2);
                ldsm4(af[1], bG + aoff + (uint32_t)((wm*32+16)*SLDH + kk*16)*2);
                #pragma unroll
                for (int ntp=0;ntp<2;ntp++){
                    uint32_t bq[4];
                    ldsm4(bq, bw + boff4 + (uint32_t)((wn*32+ntp*16)*SLDH + kk*16)*2);
                    mma16(c2[0][2*ntp],   af[0], bq);
                    mma16(c2[1][2*ntp],   af[1], bq);
                    mma16(c2[0][2*ntp+1], af[0], bq+2);
                    mma16(c2[1][2*ntp+1], af[1], bq+2);
                }
            }
        }
        cpa_wait0();
        __syncthreads();
    }

    // ---- h = relu(gate*c2 + bh1) -> float buffer (reuse sX) ----
    float* sH = (float*)sX;   // [128][66]
    #pragma unroll
    for (int mt=0;mt<2;mt++){
        int row0 = wm*32+mt*16+grp;
        float ga = sGate[row0], gb = sGate[row0+8];
        #pragma unroll
        for (int nt=0;nt<4;nt++){
            int col = wn*32+nt*8+2*tq;
            sH[row0*66+col]       = fmaxf(ga*c2[mt][nt][0]+sbh1[col],   0.f);
            sH[row0*66+col+1]     = fmaxf(ga*c2[mt][nt][1]+sbh1[col+1], 0.f);
            sH[(row0+8)*66+col]   = fmaxf(gb*c2[mt][nt][2]+sbh1[col],   0.f);
            sH[(row0+8)*66+col+1] = fmaxf(gb*c2[mt][nt][3]+sbh1[col+1], 0.f);
        }
    }
    __syncthreads();
    // ---- final 64->8 + sigmoid (2 threads/row) ----
    {
        int row = tid>>1, c0 = (tid&1)*4;
        int token = sSrc[row];
        if (token>=0){
            float acc0=sbh2[c0], acc1=sbh2[c0+1], acc2=sbh2[c0+2], acc3=sbh2[c0+3];
            #pragma unroll 8
            for (int k2=0;k2<64;k2++){
                float hv = sH[row*66+k2];
                acc0 += hv*sWh2[k2*8+c0];
                acc1 += hv*sWh2[k2*8+c0+1];
                acc2 += hv*sWh2[k2*8+c0+2];
                acc3 += hv*sWh2[k2*8+c0+3];
            }
            float* o = outR + (size_t)token*8 + c0;
            o[0] = 1.f/(1.f+__expf(-acc0));
            o[1] = 1.f/(1.f+__expf(-acc1));
            o[2] = 1.f/(1.f+__expf(-acc2));
            o[3] = 1.f/(1.f+__expf(-acc3));
        }
    }
}

// ---------------- k_aux ----------------
__global__ void k_aux(float* __restrict__ aux){
    if (threadIdx.x==0){
        double sp=0.0, cp[4]={0,0,0,0};
        for (int t=0;t<NT;t++){
            double frac = (double)g_fill[t]/(double)BTOK;
            double mp = g_sumP[t]/(double)BTOK;
            sp += frac*mp;
            cp[t>>2] += mp;
        }
        double sparsity = 16.0*sp;
        double tern = g_res[0]/1048576.0 + g_res[1]/1048576.0;
        double divv = 0.0;
        for (int i=0;i<4;i++) divv += cp[i]*log(cp[i]+1e-9);
        aux[0] = (float)(0.01*tern + 0.005*sparsity + 0.01*divv);
    }
}

// ---------------- launch ----------------
extern "C" void kernel_launch(void* const* d_in, const int* in_sizes, int n_in,
                              void* d_out, int out_size){
    const int *op=nullptr,*a=nullptr,*b=nullptr,*c=nullptr;
    const float *oe=nullptr,*Win=nullptr,*bin=nullptr,*Wr=nullptr,*W1=nullptr,*W2=nullptr;
    const float *Wh1=nullptr,*bh1=nullptr,*Wh2=nullptr,*bh2=nullptr;
    int nb_=0, nw=0;
    for (int i=0;i<n_in;i++){
        int s = in_sizes[i]; void* p = (void*)d_in[i];
        switch(s){
            case BTOK:
                if(nb_==0) op=(const int*)p; else if(nb_==1) a=(const int*)p;
                else if(nb_==2) b=(const int*)p; else c=(const int*)p;
                nb_++; break;
            case 256:  oe=(const float*)p; break;
            case 6272: Win=(const float*)p; break;
            case 128:  bin=(const float*)p; break;
            case 2048: Wr=(const float*)p; break;
            case 1048576: if(nw==0) W1=(const float*)p; else W2=(const float*)p; nw++; break;
            case 8192: Wh1=(const float*)p; break;
            case 64:   bh1=(const float*)p; break;
            case 512:  Wh2=(const float*)p; break;
            case 8:    bh2=(const float*)p; break;
            default: break;
        }
    }
    float* out = (float*)d_out;
    int smem = 4*128*SLDH*2;
    cudaFuncSetAttribute(k_ffn, cudaFuncAttributeMaxDynamicSharedMemorySize, smem);

    k_init<<<1,32>>>();
    k_tables<<<260,256>>>(oe,Win);
    k_lt<<<33,256>>>(Wr,Win,bin);
    k_scalep<<<512,256>>>(W1,W2);
    k_sfin<<<1,32>>>();
    k_quant<<<256,256>>>(W1,W2);
    k_wc<<<256,256>>>(Wh1);
    k_route<<<BTOK/256,256>>>(op,a,b,c,out + (size_t)BTOK*8);
    k_part<<<1,256>>>();
    k_ffn<<<MAXBLK,256,smem>>>(op,a,b,c,Win,bin,bh1,Wh2,bh2,out);
    k_aux<<<1,32>>>(out + (size_t)BTOK*9);
}

// round 11
// speedup vs baseline: 2.3063x; 1.6528x over previous
#include <cuda_runtime.h>
#include <cuda_fp16.h>
#include <cstdint>

#define BTOK 262144
#define DM 128
#define DFF 512
#define NT 16
#define NOPS 8
#define EMB 32
#define MROWS 128
#define SLDH 136
#define MAXBLK (BTOK/MROWS + NT)
#define TSTR (BTOK + 128)

// ---------------- device scratch ----------------
__device__ float g_Tf[NOPS*DM];
__device__ float g_Tg[256*DM];
__device__ float g_Th[256*DM];
__device__ float g_Lf[NOPS*NT];
__device__ float g_Lg[256*NT];
__device__ float g_Lh[256*NT];
__device__ float g_Lc[NT];
__device__ float g_Lb[NT];
__device__ float g_s1[NT], g_s2[NT];
__device__ double g_sabs[32];
__device__ double g_res[2];
__device__ __half g_W1h[NT*DFF*DM];   // [t][n(dff)][k(d)]
__device__ __half g_W2h[NT*DM*DFF];   // [t][nn(d)][kk(dff)]
__device__ __half g_Wch[NT*64*DFF];   // [t][n(64)][k(dff)] = s2 * W2q @ Wh1
__device__ float  g_U[NT*50*DFF];     // [t][f(49)+bias][n(dff)] = Win @ W1q (+bias row)
__device__ __half g_T1g[NT*256*DFF];  // s1 * (bits(a) rows)   4MB
__device__ __half g_T1h[NT*256*DFF];  // s1 * (bits(b) rows)   4MB
__device__ __half g_T1fc[NT*NOPS*2*DFF]; // s1*(emb@U + c + bias) 256KB
__device__ double g_sumP[NT];
__device__ int g_fill[NT];
__device__ int g_nblocks;
__device__ float g_gate[BTOK];
__device__ int g_src[NT*TSTR];
__device__ int g_bmT[MAXBLK];
__device__ int g_bmR[MAXBLK];

// ---------------- helpers ----------------
__device__ __forceinline__ float tanh_fast(float v){
    float r; asm("tanh.approx.f32 %0, %1;" : "=f"(r) : "f"(v)); return r;
}
__device__ __forceinline__ float gelu1(float v){
    return 0.5f*v*(1.f+tanh_fast(0.7978845608f*(v+0.044715f*v*v*v)));
}
__device__ __forceinline__ uint32_t smem_u32(const void* p){
    uint32_t a;
    asm("{ .reg .u64 t; cvta.to.shared.u64 t, %1; cvt.u32.u64 %0, t; }":"=r"(a):"l"(p));
    return a;
}
__device__ __forceinline__ void ldsm4(uint32_t* r, uint32_t addr){
    asm volatile("ldmatrix.sync.aligned.m8n8.x4.shared.b16 {%0,%1,%2,%3}, [%4];"
        : "=r"(r[0]),"=r"(r[1]),"=r"(r[2]),"=r"(r[3]) : "r"(addr));
}
__device__ __forceinline__ void mma16(float* c, const uint32_t* a, const uint32_t* b){
    asm volatile("mma.sync.aligned.m16n8k16.row.col.f32.f16.f16.f32 "
        "{%0,%1,%2,%3},{%4,%5,%6,%7},{%8,%9},{%0,%1,%2,%3};"
        : "+f"(c[0]),"+f"(c[1]),"+f"(c[2]),"+f"(c[3])
        : "r"(a[0]),"r"(a[1]),"r"(a[2]),"r"(a[3]),"r"(b[0]),"r"(b[1]));
}
__device__ __forceinline__ __half2 h2pack(float a, float b){
    return __floats2half2_rn(a, b);
}
__device__ __forceinline__ void cpa16(uint32_t dst, const void* src){
    asm volatile("cp.async.cg.shared.global [%0], [%1], 16;" :: "r"(dst),"l"(src):"memory");
}
__device__ __forceinline__ void cpa_commit(){
    asm volatile("cp.async.commit_group;":::"memory");
}
__device__ __forceinline__ void cpa_wait0(){
    asm volatile("cp.async.wait_group 0;":::"memory");
}
__device__ __forceinline__ void cpa_wait1(){
    asm volatile("cp.async.wait_group 1;":::"memory");
}

// ---------------- k_init ----------------
__global__ void k_init(){
    int i = threadIdx.x;
    if (i < NT){ g_sumP[i]=0.0; g_fill[i]=0; }
    if (i < 32) g_sabs[i]=0.0;
    if (i < 2)  g_res[i]=0.0;
}

// ---------------- k_tables (router feature tables, D-domain) ----------------
__global__ void k_tables(const float* __restrict__ oe, const float* __restrict__ Win){
    int gid = blockIdx.x*256 + threadIdx.x;
    if (gid < 32768){
        int av = gid >> 7, d = gid & 127;
        float s = 0.f;
        #pragma unroll
        for (int i=0;i<8;i++) if ((av>>i)&1) s += Win[(32+i)*DM + d];
        g_Tg[av*DM+d] = s;
    } else if (gid < 65536){
        int g2 = gid - 32768;
        int bv = g2 >> 7, d = g2 & 127;
        float s = 0.f;
        #pragma unroll
        for (int i=0;i<8;i++) if ((bv>>i)&1) s += Win[(40+i)*DM + d];
        g_Th[bv*DM+d] = s;
    } else if (gid < 66560){
        int g2 = gid - 65536;
        int op = g2 >> 7, d = g2 & 127;
        float s = 0.f;
        #pragma unroll
        for (int j=0;j<EMB;j++) s += oe[op*EMB+j]*Win[j*DM+d];
        g_Tf[op*DM+d] = s;
    }
}

// ---------------- k_lt (router logit tables) ----------------
__global__ void k_lt(const float* __restrict__ Wr, const float* __restrict__ Win,
                     const float* __restrict__ bin){
    int gid = blockIdx.x*256+threadIdx.x;
    if (gid < 4096){
        int av=gid>>4, t=gid&15; float s=0.f;
        for(int d=0;d<DM;d++) s += g_Tg[av*DM+d]*Wr[d*NT+t];
        g_Lg[gid]=s;
    } else if (gid < 8192){
        int g2=gid-4096; int bv=g2>>4,t=g2&15; float s=0.f;
        for(int d=0;d<DM;d++) s += g_Th[bv*DM+d]*Wr[d*NT+t];
        g_Lh[g2]=s;
    } else if (gid < 8320){
        int g2=gid-8192; int op=g2>>4,t=g2&15; float s=0.f;
        for(int d=0;d<DM;d++) s += g_Tf[op*DM+d]*Wr[d*NT+t];
        g_Lf[g2]=s;
    } else if (gid < 8336){
        int t=gid-8320; float s=0.f;
        for(int d=0;d<DM;d++) s += Win[48*DM+d]*Wr[d*NT+t];
        g_Lc[t]=s;
    } else if (gid < 8352){
        int t=gid-8336; float s=0.f;
        for(int d=0;d<DM;d++) s += bin[d]*Wr[d*NT+t];
        g_Lb[t]=s;
    }
}

// ---------------- k_scalep ----------------
__global__ void k_scalep(const float* __restrict__ W1, const float* __restrict__ W2){
    __shared__ double red[256];
    int tile = blockIdx.x >> 4;
    int sub  = blockIdx.x & 15;
    const float* W = (tile < 16 ? W1 + tile*65536 : W2 + (tile-16)*65536) + sub*4096;
    const float4* W4 = (const float4*)W;
    double s = 0.0;
    #pragma unroll
    for (int r=0;r<4;r++){
        float4 v = W4[threadIdx.x + r*256];
        s += (double)(fabsf(v.x)+fabsf(v.y)+fabsf(v.z)+fabsf(v.w));
    }
    red[threadIdx.x]=s; __syncthreads();
    for (int o=128;o;o>>=1){ if(threadIdx.x<o) red[threadIdx.x]+=red[threadIdx.x+o]; __syncthreads(); }
    if (!threadIdx.x) atomicAdd(&g_sabs[tile], red[0]);
}

// ---------------- k_sfin ----------------
__global__ void k_sfin(){
    int t = threadIdx.x;
    if (t < 16) g_s1[t] = (float)(g_sabs[t]/65536.0);
    else if (t < 32) g_s2[t-16] = (float)(g_sabs[t]/65536.0);
}

// ---------------- k_quant: coalesced transpose via smem ----------------
__global__ void k_quant(const float* __restrict__ W1, const float* __restrict__ W2){
    __shared__ __half sh[64*130];
    __shared__ double red[256];
    int b = blockIdx.x, tid = threadIdx.x;
    double racc = 0.0;
    if (b < 128){
        int t = b>>3, n0 = (b&7)*64;
        float s = g_s1[t];
        const float* src = W1 + t*65536;
        #pragma unroll
        for (int j=0;j<32;j++){
            int i = tid + j*256;
            int k = i>>6, nx = i&63;
            float w = src[k*512 + n0 + nx];
            float aw = fabsf(w);
            bool nz = aw > 0.7f*s;
            float q = nz ? (w>0.f?1.f:-1.f) : 0.f;
            racc += (double)(nz ? fabsf(aw - s) : aw);
            sh[nx*130 + k] = __float2half(q);
        }
        __syncthreads();
        __half* dst = g_W1h + t*65536 + n0*128;
        #pragma unroll
        for (int j=0;j<32;j++){
            int i = tid + j*256;
            int n = i>>7, k = i&127;
            dst[n*128 + k] = sh[n*130 + k];
        }
        red[tid]=racc; __syncthreads();
        for(int o=128;o;o>>=1){ if(tid<o) red[tid]+=red[tid+o]; __syncthreads(); }
        if (!tid) atomicAdd(&g_res[0], red[0]);
    } else {
        int bb = b-128;
        int t = bb>>3, kk0 = (bb&7)*64;
        float s = g_s2[t];
        const float* src = W2 + t*65536;
        #pragma unroll
        for (int j=0;j<32;j++){
            int i = tid + j*256;
            int kk = i>>7, nn = i&127;
            float w = src[(kk0+kk)*128 + nn];
            float aw = fabsf(w);
            bool nz = aw > 0.7f*s;
            float q = nz ? (w>0.f?1.f:-1.f) : 0.f;
            racc += (double)(nz ? fabsf(aw - s) : aw);
            sh[kk*130 + nn] = __float2half(q);
        }
        __syncthreads();
        __half* dst = g_W2h + t*65536 + kk0;
        #pragma unroll
        for (int j=0;j<32;j++){
            int i = tid + j*256;
            int nn = i>>6, kx = i&63;
            dst[nn*512 + kx] = sh[kx*130 + nn];
        }
        red[tid]=racc; __syncthreads();
        for(int o=128;o;o>>=1){ if(tid<o) red[tid]+=red[tid+o]; __syncthreads(); }
        if (!tid) atomicAdd(&g_res[1], red[0]);
    }
}

// ---------------- k_wc: Wc[t][n][k] = s2 * sum_d W2q[t][d][k] * Wh1[d][n] ----------------
__global__ void k_wc(const float* __restrict__ Wh1){
    __shared__ float sWh1[128*64];
    __shared__ __half sW2[128*32];
    int b = blockIdx.x, tid = threadIdx.x;
    int t = b>>4, k0 = (b&15)*32;
    float s2 = g_s2[t];
    #pragma unroll
    for (int j=0;j<32;j++) sWh1[tid + j*256] = Wh1[tid + j*256];
    const __half* W2p = g_W2h + t*65536 + k0;
    #pragma unroll
    for (int j=0;j<16;j++){
        int i = tid + j*256;
        int d = i>>5, kx = i&31;
        sW2[d*32 + kx] = W2p[d*512 + kx];
    }
    __syncthreads();
    #pragma unroll
    for (int j=0;j<8;j++){
        int o = tid + j*256;
        int n = o&63, kx = o>>6;
        float acc = 0.f;
        #pragma unroll 8
        for (int d=0; d<128; d++)
            acc += __half2float(sW2[d*32 + kx]) * sWh1[d*64 + n];
        g_Wch[t*32768 + n*512 + k0 + kx] = __float2half(s2*acc);
    }
}

// ---------------- k_u: U[t][f][n] = sum_d Win[f][d] * W1q[t][n][d]  (f=49 -> bias) ----------------
// grid 128: t = b>>3, n0 = (b&7)*64
__global__ void k_u(const float* __restrict__ Win, const float* __restrict__ bin){
    __shared__ float sWin[50*128];
    __shared__ __half sW[64*128];
    int b = blockIdx.x, tid = threadIdx.x;
    int t = b>>3, n0 = (b&7)*64;
    for (int i=tid; i<6400; i+=256) sWin[i] = (i<6272) ? Win[i] : bin[i-6272];
    const __half* src = g_W1h + t*65536 + n0*128;
    #pragma unroll
    for (int j=0;j<32;j++) sW[tid + j*256] = src[tid + j*256];
    __syncthreads();
    for (int o=tid; o<3200; o+=256){
        int f = o>>6, n = o&63;
        float acc = 0.f;
        #pragma unroll 8
        for (int d=0; d<128; d++)
            acc += sWin[f*128+d] * __half2float(sW[n*128+d]);
        g_U[(t*50+f)*512 + n0 + n] = acc;
    }
}

// ---------------- k_tg: T1g / T1h tables (s1 folded) ----------------
// grid 32: t = b>>1, which = b&1 (0:a-bits rows 32..39, 1:b-bits rows 40..47)
__global__ void k_tg(){
    __shared__ float sU[8*512];
    int b = blockIdx.x, tid = threadIdx.x;
    int t = b>>1, which = b&1;
    for (int i=tid; i<4096; i+=256)
        sU[i] = g_U[(t*50 + 32 + which*8 + (i>>9))*512 + (i&511)];
    float s1 = g_s1[t];
    __half* dst = (which ? g_T1h : g_T1g) + ((size_t)t<<17);
    __syncthreads();
    for (int o=tid; o<131072; o+=256){
        int av = o>>9, n = o&511;
        float acc = 0.f;
        #pragma unroll
        for (int i=0;i<8;i++) if ((av>>i)&1) acc += sU[i*512+n];
        dst[o] = __float2half(s1*acc);
    }
}

// ---------------- k_tfc: T1fc[t][op][c][n] (s1 folded, includes bias) ----------------
__global__ void k_tfc(const float* __restrict__ oe){
    int t = blockIdx.x, tid = threadIdx.x;
    float s1 = g_s1[t];
    for (int o=tid; o<8192; o+=256){
        int n = o&511, cc = (o>>9)&1, opv = o>>10;
        float acc = g_U[(t*50+49)*512+n];           // bias row
        if (cc) acc += g_U[(t*50+48)*512+n];        // c feature
        #pragma unroll 8
        for (int j=0;j<32;j++)
            acc += oe[opv*32+j] * g_U[(t*50+j)*512+n];
        g_T1fc[t*8192 + o] = __float2half(s1*acc);
    }
}

// ---------------- k_route ----------------
__global__ void k_route(const int* __restrict__ op, const int* __restrict__ a,
                        const int* __restrict__ b, const int* __restrict__ c,
                        float* __restrict__ outIdx){
    __shared__ float sLf[NOPS*NT], sLg[256*NT], sLh[256*NT], sLc[NT], sLb[NT];
    __shared__ float sP[NT]; __shared__ int sC[NT]; __shared__ int sBase[NT];
    int tid = threadIdx.x;
    int lane = tid & 31;
    for (int i=tid;i<256*NT;i+=256){ sLg[i]=g_Lg[i]; sLh[i]=g_Lh[i]; }
    for (int i=tid;i<NOPS*NT;i+=256) sLf[i]=g_Lf[i];
    if (tid<NT){ sLc[tid]=g_Lc[tid]; sLb[tid]=g_Lb[tid]; sP[tid]=0.f; sC[tid]=0; }
    __syncthreads();
    int i = blockIdx.x*256+tid;
    int opv=op[i], av=a[i], bv=b[i]; float cv=(float)c[i];
    float l[NT]; float mx=-1e30f; int best=0;
    #pragma unroll
    for (int t=0;t<NT;t++){
        float v = sLf[opv*NT+t]+sLg[av*NT+t]+sLh[bv*NT+t]+cv*sLc[t]+sLb[t];
        l[t]=v;
        if (v>mx){mx=v;best=t;}
    }
    float den=0.f;
    #pragma unroll
    for (int t=0;t<NT;t++){ l[t]=__expf(l[t]-mx); den+=l[t]; }
    float inv = 1.f/den;
    #pragma unroll
    for (int t=0;t<NT;t++){
        float v = l[t]*inv;
        #pragma unroll
        for (int o=16;o;o>>=1) v += __shfl_xor_sync(0xffffffffu, v, o);
        if (lane==0) atomicAdd(&sP[t], v);
    }
    int rank = atomicAdd(&sC[best], 1);
    g_gate[i]=inv; outIdx[i]=(float)best;
    __syncthreads();
    if (tid<NT){
        sBase[tid] = atomicAdd(&g_fill[tid], sC[tid]);
        atomicAdd(&g_sumP[tid], (double)sP[tid]);
    }
    __syncthreads();
    g_src[best*TSTR + sBase[best] + rank] = i;
}

// ---------------- k_part ----------------
__global__ void k_part(){
    __shared__ int pc[NT], po_[NT];
    int tid=threadIdx.x;
    if (tid<NT) pc[tid] = g_fill[tid];
    __syncthreads();
    if (tid==0){
        int nb=0;
        for (int t=0;t<NT;t++){ po_[t]=nb; nb += (pc[t]+MROWS-1)/MROWS; }
        g_nblocks = nb;
    }
    __syncthreads();
    for (int t=0;t<NT;t++){
        int bl = (pc[t]+MROWS-1)/MROWS;
        for (int bi=tid; bi<bl; bi+=256){ g_bmT[po_[t]+bi]=t; g_bmR[po_[t]+bi]=t*TSTR + bi*MROWS; }
        int cnt=pc[t]; int pad = bl*MROWS;
        for (int p=cnt+tid; p<pad; p+=256) g_src[t*TSTR+p] = -1;
    }
}

// ---------------- k_ffn: table-based gelu input + fused GEMM2+head ----------------
__global__ void __launch_bounds__(256,2) k_ffn(
    const int* __restrict__ op, const int* __restrict__ aIn,
    const int* __restrict__ bIn, const int* __restrict__ cIn,
    const float* __restrict__ bh1,
    const float* __restrict__ Wh2, const float* __restrict__ bh2,
    float* __restrict__ outR)
{
    extern __shared__ __half sm[];
    __half* sG  = sm;                       // [128][SLDH]
    __half* sW0 = sm + 128*SLDH;            // [64][SLDH]
    __half* sW1 = sW0 + 64*SLDH;            // [64][SLDH]
    __shared__ float sGate[MROWS];
    __shared__ int   sSrc[MROWS];
    __shared__ int   sAV[MROWS], sBV[MROWS], sOC[MROWS];
    __shared__ float sWh2[512], sbh1[64], sbh2[8];

    int bid = blockIdx.x;
    if (bid >= g_nblocks) return;
    int t  = g_bmT[bid], r0 = g_bmR[bid];
    int tid = threadIdx.x;
    int wid = tid>>5, lane = tid&31;
    int grp = lane>>2, tq = lane&3;
    int wm = wid&3, wn = wid>>2;            // 4 m-warps x 2 n-warps
    int lt8 = lane>>3, lc8 = lane&7;

    uint32_t bG = smem_u32(sG);
    uint32_t bufs[2] = { smem_u32(sW0), smem_u32(sW1) };
    uint32_t aoff  = (uint32_t)((lane&15)*SLDH + (lane>>4)*8)*2;
    uint32_t boff4 = (uint32_t)(((lane&7) + ((lane>>4)<<3))*SLDH + ((lane>>3)&1)*8)*2;

    const __half* Wcp = g_Wch + t*32768;

    // ---- prefetch Wc chunk 0 ----
    {
        #pragma unroll
        for (int j=0;j<4;j++){
            int i = tid + j*256;
            int row = i>>4, ck = i&15;
            cpa16(bufs[0] + (uint32_t)(row*SLDH + ck*8)*2, Wcp + row*512 + ck*8);
        }
        cpa_commit();
    }

    // ---- per-row caches ----
    if (tid < 128){
        int token = g_src[r0+tid];
        sSrc[tid] = token;
        if (token>=0){
            sGate[tid] = g_gate[token];
            sAV[tid] = aIn[token];
            sBV[tid] = bIn[token];
            sOC[tid] = (t*8 + op[token])*2 + cIn[token];
        } else {
            sGate[tid]=0.f; sAV[tid]=0; sBV[tid]=0; sOC[tid]=t*16;
        }
    }
    for (int i=tid;i<512;i+=256) sWh2[i]=Wh2[i];
    if (tid<64) sbh1[tid]=bh1[tid];
    if (tid<8)  sbh2[tid]=bh2[tid];

    float c2[2][4][4];
    #pragma unroll
    for(int mt=0;mt<2;mt++)
        #pragma unroll
        for(int nt=0;nt<4;nt++)
            #pragma unroll
            for(int e=0;e<4;e++) c2[mt][nt][e]=0.f;

    __syncthreads();

    for (int ch=0; ch<4; ch++){
        // ---- build sG chunk from tables (coalesced: 8 lanes cover one token line) ----
        #pragma unroll
        for (int p=0;p<4;p++){
            int row = p*32 + wid*4 + lt8;
            int token = sSrc[row];
            __half* dst = sG + row*SLDH + lc8*8;
            if (token>=0){
                const __half* pg = g_T1g + ((((size_t)(t<<8)+sAV[row])<<9) + ch*128 + lc8*8);
                const __half* ph = g_T1h + ((((size_t)(t<<8)+sBV[row])<<9) + ch*128 + lc8*8);
                const __half* pf = g_T1fc + (((size_t)sOC[row]<<9) + ch*128 + lc8*8);
                #pragma unroll
                for (int seg=0;seg<2;seg++){
                    int off = seg*64;
                    uint4 va = *(const uint4*)(pg+off);
                    uint4 vb = *(const uint4*)(ph+off);
                    uint4 vf = *(const uint4*)(pf+off);
                    const __half2* ha=(const __half2*)&va;
                    const __half2* hb=(const __half2*)&vb;
                    const __half2* hf=(const __half2*)&vf;
                    uint4 ou;
                    __half2* ho = (__half2*)&ou;
                    #pragma unroll
                    for (int q=0;q<4;q++){
                        float2 fa = __half22float2(ha[q]);
                        float2 fb = __half22float2(hb[q]);
                        float2 ff = __half22float2(hf[q]);
                        float v0 = fa.x+fb.x+ff.x;
                        float v1 = fa.y+fb.y+ff.y;
                        ho[q] = h2pack(gelu1(v0), gelu1(v1));
                    }
                    *(uint4*)(dst+off) = ou;
                }
            } else {
                uint4 z = make_uint4(0,0,0,0);
                *(uint4*)(dst)    = z;
                *(uint4*)(dst+64) = z;
            }
        }
        // ---- prefetch next Wc chunk ----
        if (ch<3){
            uint32_t dstb = bufs[(ch+1)&1];
            const __half* src = Wcp + (ch+1)*128;
            #pragma unroll
            for (int j=0;j<4;j++){
                int i = tid + j*256;
                int row = i>>4, ck = i&15;
                cpa16(dstb + (uint32_t)(row*SLDH + ck*8)*2, src + row*512 + ck*8);
            }
            cpa_commit();
            cpa_wait1();
        } else {
            cpa_wait0();
        }
        __syncthreads();
        // ---- fused GEMM2+head mma: sG @ Wc[ch] (N=64, K=128) ----
        uint32_t bw = bufs[ch&1];
        #pragma unroll
        for (int kk=0;kk<8;kk++){
            uint32_t af[2][4];
            ldsm4(af[0], bG + aoff + (uint32_t)((wm*32)*SLDH + kk*16)*2);
            ldsm4(af[1], bG + aoff + (uint32_t)((wm*32+16)*SLDH + kk*16)*2);
            #pragma unroll
            for (int ntp=0;ntp<2;ntp++){
                uint32_t bq[4];
                ldsm4(bq, bw + boff4 + (uint32_t)((wn*32+ntp*16)*SLDH + kk*16)*2);
                mma16(c2[0][2*ntp],   af[0], bq);
                mma16(c2[1][2*ntp],   af[1], bq);
                mma16(c2[0][2*ntp+1], af[0], bq+2);
                mma16(c2[1][2*ntp+1], af[1], bq+2);
            }
        }
        __syncthreads();
    }

    // ---- h = relu(gate*c2 + bh1) -> float buffer (reuse sG) ----
    float* sH = (float*)sG;   // [128][66]
    #pragma unroll
    for (int mt=0;mt<2;mt++){
        int row0 = wm*32+mt*16+grp;
        float ga = sGate[row0], gb = sGate[row0+8];
        #pragma unroll
        for (int nt=0;nt<4;nt++){
            int col = wn*32+nt*8+2*tq;
            sH[row0*66+col]       = fmaxf(ga*c2[mt][nt][0]+sbh1[col],   0.f);
            sH[row0*66+col+1]     = fmaxf(ga*c2[mt][nt][1]+sbh1[col+1], 0.f);
            sH[(row0+8)*66+col]   = fmaxf(gb*c2[mt][nt][2]+sbh1[col],   0.f);
            sH[(row0+8)*66+col+1] = fmaxf(gb*c2[mt][nt][3]+sbh1[col+1], 0.f);
        }
    }
    __syncthreads();
    // ---- final 64->8 + sigmoid (2 threads/row) ----
    {
        int row = tid>>1, c0 = (tid&1)*4;
        int token = sSrc[row];
        if (token>=0){
            float acc0=sbh2[c0], acc1=sbh2[c0+1], acc2=sbh2[c0+2], acc3=sbh2[c0+3];
            #pragma unroll 8
            for (int k2=0;k2<64;k2++){
                float hv = sH[row*66+k2];
                acc0 += hv*sWh2[k2*8+c0];
                acc1 += hv*sWh2[k2*8+c0+1];
                acc2 += hv*sWh2[k2*8+c0+2];
                acc3 += hv*sWh2[k2*8+c0+3];
            }
            float* o = outR + (size_t)token*8 + c0;
            o[0] = 1.f/(1.f+__expf(-acc0));
            o[1] = 1.f/(1.f+__expf(-acc1));
            o[2] = 1.f/(1.f+__expf(-acc2));
            o[3] = 1.f/(1.f+__expf(-acc3));
        }
    }
}

// ---------------- k_aux ----------------
__global__ void k_aux(float* __restrict__ aux){
    if (threadIdx.x==0){
        double sp=0.0, cp[4]={0,0,0,0};
        for (int t=0;t<NT;t++){
            double frac = (double)g_fill[t]/(double)BTOK;
            double mp = g_sumP[t]/(double)BTOK;
            sp += frac*mp;
            cp[t>>2] += mp;
        }
        double sparsity = 16.0*sp;
        double tern = g_res[0]/1048576.0 + g_res[1]/1048576.0;
        double divv = 0.0;
        for (int i=0;i<4;i++) divv += cp[i]*log(cp[i]+1e-9);
        aux[0] = (float)(0.01*tern + 0.005*sparsity + 0.01*divv);
    }
}

// ---------------- launch ----------------
extern "C" void kernel_launch(void* const* d_in, const int* in_sizes, int n_in,
                              void* d_out, int out_size){
    const int *op=nullptr,*a=nullptr,*b=nullptr,*c=nullptr;
    const float *oe=nullptr,*Win=nullptr,*bin=nullptr,*Wr=nullptr,*W1=nullptr,*W2=nullptr;
    const float *Wh1=nullptr,*bh1=nullptr,*Wh2=nullptr,*bh2=nullptr;
    int nb_=0, nw=0;
    for (int i=0;i<n_in;i++){
        int s = in_sizes[i]; void* p = (void*)d_in[i];
        switch(s){
            case BTOK:
                if(nb_==0) op=(const int*)p; else if(nb_==1) a=(const int*)p;
                else if(nb_==2) b=(const int*)p; else c=(const int*)p;
                nb_++; break;
            case 256:  oe=(const float*)p; break;
            case 6272: Win=(const float*)p; break;
            case 128:  bin=(const float*)p; break;
            case 2048: Wr=(const float*)p; break;
            case 1048576: if(nw==0) W1=(const float*)p; else W2=(const float*)p; nw++; break;
            case 8192: Wh1=(const float*)p; break;
            case 64:   bh1=(const float*)p; break;
            case 512:  Wh2=(const float*)p; break;
            case 8:    bh2=(const float*)p; break;
            default: break;
        }
    }
    float* out = (float*)d_out;
    int smem = 256*SLDH*2;   // sG(128) + sW0(64) + sW1(64) rows
    cudaFuncSetAttribute(k_ffn, cudaFuncAttributeMaxDynamicSharedMemorySize, smem);

    k_init<<<1,32>>>();
    k_tables<<<260,256>>>(oe,Win);
    k_lt<<<33,256>>>(Wr,Win,bin);
    k_scalep<<<512,256>>>(W1,W2);
    k_sfin<<<1,32>>>();
    k_quant<<<256,256>>>(W1,W2);
    k_wc<<<256,256>>>(Wh1);
    k_u<<<128,256>>>(Win,bin);
    k_tg<<<32,256>>>();
    k_tfc<<<16,256>>>(oe);
    k_route<<<BTOK/256,256>>>(op,a,b,c,out + (size_t)BTOK*8);
    k_part<<<1,256>>>();
    k_ffn<<<MAXBLK,256,smem>>>(op,a,b,c,bh1,Wh2,bh2,out);
    k_aux<<<1,32>>>(out + (size_t)BTOK*9);
}

// round 12
// speedup vs baseline: 2.4561x; 1.0650x over previous
#include <cuda_runtime.h>
#include <cuda_fp16.h>
#include <cstdint>

#define BTOK 262144
#define DM 128
#define DFF 512
#define NT 16
#define NOPS 8
#define EMB 32
#define MROWS 128
#define SLDH 136
#define MAXBLK (BTOK/MROWS + NT)
#define TSTR (BTOK + 128)

// ---------------- device scratch ----------------
__device__ float g_Tf[NOPS*DM];
__device__ float g_Tg[256*DM];
__device__ float g_Th[256*DM];
__device__ float g_Lf[NOPS*NT];
__device__ float g_Lg[256*NT];
__device__ float g_Lh[256*NT];
__device__ float g_Lc[NT];
__device__ float g_Lb[NT];
__device__ float g_s1[NT], g_s2[NT];
__device__ double g_sabs[32];
__device__ double g_res[2];
__device__ __half g_W1h[NT*DFF*DM];   // [t][n(dff)][k(d)]
__device__ __half g_W2h[NT*DM*DFF];   // [t][nn(d)][kk(dff)]
__device__ __half g_Wch[NT*64*DFF];   // [t][n(64)][k(dff)] = s2 * W2q @ Wh1
__device__ float  g_U[NT*50*DFF];     // [t][f(49)+bias][n(dff)]
__device__ __half g_T1g[NT*256*DFF];
__device__ __half g_T1h[NT*256*DFF];
__device__ __half g_T1fc[NT*NOPS*2*DFF];
__device__ double g_sumP[NT];
__device__ int g_fill[NT];
__device__ int g_nblocks;
__device__ float g_gate[BTOK];
__device__ int g_src[NT*TSTR];
__device__ int g_bmT[MAXBLK];
__device__ int g_bmR[MAXBLK];

// ---------------- helpers ----------------
__device__ __forceinline__ uint32_t smem_u32(const void* p){
    uint32_t a;
    asm("{ .reg .u64 t; cvta.to.shared.u64 t, %1; cvt.u32.u64 %0, t; }":"=r"(a):"l"(p));
    return a;
}
__device__ __forceinline__ void ldsm4(uint32_t* r, uint32_t addr){
    asm volatile("ldmatrix.sync.aligned.m8n8.x4.shared.b16 {%0,%1,%2,%3}, [%4];"
        : "=r"(r[0]),"=r"(r[1]),"=r"(r[2]),"=r"(r[3]) : "r"(addr));
}
__device__ __forceinline__ void mma16(float* c, const uint32_t* a, const uint32_t* b){
    asm volatile("mma.sync.aligned.m16n8k16.row.col.f32.f16.f16.f32 "
        "{%0,%1,%2,%3},{%4,%5,%6,%7},{%8,%9},{%0,%1,%2,%3};"
        : "+f"(c[0]),"+f"(c[1]),"+f"(c[2]),"+f"(c[3])
        : "r"(a[0]),"r"(a[1]),"r"(a[2]),"r"(a[3]),"r"(b[0]),"r"(b[1]));
}
__device__ __forceinline__ __half2 h2pack(float a, float b){
    return __floats2half2_rn(a, b);
}
__device__ __forceinline__ void cpa16(uint32_t dst, const void* src){
    asm volatile("cp.async.cg.shared.global [%0], [%1], 16;" :: "r"(dst),"l"(src):"memory");
}
__device__ __forceinline__ void cpa_commit(){
    asm volatile("cp.async.commit_group;":::"memory");
}
__device__ __forceinline__ void cpa_wait0(){
    asm volatile("cp.async.wait_group 0;":::"memory");
}
#define BAR_SYNC2(id)   asm volatile("bar.sync %0, 256;"   :: "r"(id) : "memory")
#define BAR_ARRIVE2(id) asm volatile("bar.arrive %0, 256;" :: "r"(id) : "memory")
#define BAR_SYNC_C()    asm volatile("bar.sync 5, 128;"    ::: "memory")

// ---------------- k_init ----------------
__global__ void k_init(){
    int i = threadIdx.x;
    if (i < NT){ g_sumP[i]=0.0; g_fill[i]=0; }
    if (i < 32) g_sabs[i]=0.0;
    if (i < 2)  g_res[i]=0.0;
}

// ---------------- k_tables ----------------
__global__ void k_tables(const float* __restrict__ oe, const float* __restrict__ Win){
    int gid = blockIdx.x*256 + threadIdx.x;
    if (gid < 32768){
        int av = gid >> 7, d = gid & 127;
        float s = 0.f;
        #pragma unroll
        for (int i=0;i<8;i++) if ((av>>i)&1) s += Win[(32+i)*DM + d];
        g_Tg[av*DM+d] = s;
    } else if (gid < 65536){
        int g2 = gid - 32768;
        int bv = g2 >> 7, d = g2 & 127;
        float s = 0.f;
        #pragma unroll
        for (int i=0;i<8;i++) if ((bv>>i)&1) s += Win[(40+i)*DM + d];
        g_Th[bv*DM+d] = s;
    } else if (gid < 66560){
        int g2 = gid - 65536;
        int op = g2 >> 7, d = g2 & 127;
        float s = 0.f;
        #pragma unroll
        for (int j=0;j<EMB;j++) s += oe[op*EMB+j]*Win[j*DM+d];
        g_Tf[op*DM+d] = s;
    }
}

// ---------------- k_lt ----------------
__global__ void k_lt(const float* __restrict__ Wr, const float* __restrict__ Win,
                     const float* __restrict__ bin){
    int gid = blockIdx.x*256+threadIdx.x;
    if (gid < 4096){
        int av=gid>>4, t=gid&15; float s=0.f;
        for(int d=0;d<DM;d++) s += g_Tg[av*DM+d]*Wr[d*NT+t];
        g_Lg[gid]=s;
    } else if (gid < 8192){
        int g2=gid-4096; int bv=g2>>4,t=g2&15; float s=0.f;
        for(int d=0;d<DM;d++) s += g_Th[bv*DM+d]*Wr[d*NT+t];
        g_Lh[g2]=s;
    } else if (gid < 8320){
        int g2=gid-8192; int op=g2>>4,t=g2&15; float s=0.f;
        for(int d=0;d<DM;d++) s += g_Tf[op*DM+d]*Wr[d*NT+t];
        g_Lf[g2]=s;
    } else if (gid < 8336){
        int t=gid-8320; float s=0.f;
        for(int d=0;d<DM;d++) s += Win[48*DM+d]*Wr[d*NT+t];
        g_Lc[t]=s;
    } else if (gid < 8352){
        int t=gid-8336; float s=0.f;
        for(int d=0;d<DM;d++) s += bin[d]*Wr[d*NT+t];
        g_Lb[t]=s;
    }
}

// ---------------- k_scalep ----------------
__global__ void k_scalep(const float* __restrict__ W1, const float* __restrict__ W2){
    __shared__ double red[256];
    int tile = blockIdx.x >> 4;
    int sub  = blockIdx.x & 15;
    const float* W = (tile < 16 ? W1 + tile*65536 : W2 + (tile-16)*65536) + sub*4096;
    const float4* W4 = (const float4*)W;
    double s = 0.0;
    #pragma unroll
    for (int r=0;r<4;r++){
        float4 v = W4[threadIdx.x + r*256];
        s += (double)(fabsf(v.x)+fabsf(v.y)+fabsf(v.z)+fabsf(v.w));
    }
    red[threadIdx.x]=s; __syncthreads();
    for (int o=128;o;o>>=1){ if(threadIdx.x<o) red[threadIdx.x]+=red[threadIdx.x+o]; __syncthreads(); }
    if (!threadIdx.x) atomicAdd(&g_sabs[tile], red[0]);
}

// ---------------- k_sfin ----------------
__global__ void k_sfin(){
    int t = threadIdx.x;
    if (t < 16) g_s1[t] = (float)(g_sabs[t]/65536.0);
    else if (t < 32) g_s2[t-16] = (float)(g_sabs[t]/65536.0);
}

// ---------------- k_quant ----------------
__global__ void k_quant(const float* __restrict__ W1, const float* __restrict__ W2){
    __shared__ __half sh[64*130];
    __shared__ double red[256];
    int b = blockIdx.x, tid = threadIdx.x;
    double racc = 0.0;
    if (b < 128){
        int t = b>>3, n0 = (b&7)*64;
        float s = g_s1[t];
        const float* src = W1 + t*65536;
        #pragma unroll
        for (int j=0;j<32;j++){
            int i = tid + j*256;
            int k = i>>6, nx = i&63;
            float w = src[k*512 + n0 + nx];
            float aw = fabsf(w);
            bool nz = aw > 0.7f*s;
            float q = nz ? (w>0.f?1.f:-1.f) : 0.f;
            racc += (double)(nz ? fabsf(aw - s) : aw);
            sh[nx*130 + k] = __float2half(q);
        }
        __syncthreads();
        __half* dst = g_W1h + t*65536 + n0*128;
        #pragma unroll
        for (int j=0;j<32;j++){
            int i = tid + j*256;
            int n = i>>7, k = i&127;
            dst[n*128 + k] = sh[n*130 + k];
        }
        red[tid]=racc; __syncthreads();
        for(int o=128;o;o>>=1){ if(tid<o) red[tid]+=red[tid+o]; __syncthreads(); }
        if (!tid) atomicAdd(&g_res[0], red[0]);
    } else {
        int bb = b-128;
        int t = bb>>3, kk0 = (bb&7)*64;
        float s = g_s2[t];
        const float* src = W2 + t*65536;
        #pragma unroll
        for (int j=0;j<32;j++){
            int i = tid + j*256;
            int kk = i>>7, nn = i&127;
            float w = src[(kk0+kk)*128 + nn];
            float aw = fabsf(w);
            bool nz = aw > 0.7f*s;
            float q = nz ? (w>0.f?1.f:-1.f) : 0.f;
            racc += (double)(nz ? fabsf(aw - s) : aw);
            sh[kk*130 + nn] = __float2half(q);
        }
        __syncthreads();
        __half* dst = g_W2h + t*65536 + kk0;
        #pragma unroll
        for (int j=0;j<32;j++){
            int i = tid + j*256;
            int nn = i>>6, kx = i&63;
            dst[nn*512 + kx] = sh[kx*130 + nn];
        }
        red[tid]=racc; __syncthreads();
        for(int o=128;o;o>>=1){ if(tid<o) red[tid]+=red[tid+o]; __syncthreads(); }
        if (!tid) atomicAdd(&g_res[1], red[0]);
    }
}

// ---------------- k_wc ----------------
__global__ void k_wc(const float* __restrict__ Wh1){
    __shared__ float sWh1[128*64];
    __shared__ __half sW2[128*32];
    int b = blockIdx.x, tid = threadIdx.x;
    int t = b>>4, k0 = (b&15)*32;
    float s2 = g_s2[t];
    #pragma unroll
    for (int j=0;j<32;j++) sWh1[tid + j*256] = Wh1[tid + j*256];
    const __half* W2p = g_W2h + t*65536 + k0;
    #pragma unroll
    for (int j=0;j<16;j++){
        int i = tid + j*256;
        int d = i>>5, kx = i&31;
        sW2[d*32 + kx] = W2p[d*512 + kx];
    }
    __syncthreads();
    #pragma unroll
    for (int j=0;j<8;j++){
        int o = tid + j*256;
        int n = o&63, kx = o>>6;
        float acc = 0.f;
        #pragma unroll 8
        for (int d=0; d<128; d++)
            acc += __half2float(sW2[d*32 + kx]) * sWh1[d*64 + n];
        g_Wch[t*32768 + n*512 + k0 + kx] = __float2half(s2*acc);
    }
}

// ---------------- k_u ----------------
__global__ void k_u(const float* __restrict__ Win, const float* __restrict__ bin){
    __shared__ float sWin[50*128];
    __shared__ __half sW[64*128];
    int b = blockIdx.x, tid = threadIdx.x;
    int t = b>>3, n0 = (b&7)*64;
    for (int i=tid; i<6400; i+=256) sWin[i] = (i<6272) ? Win[i] : bin[i-6272];
    const __half* src = g_W1h + t*65536 + n0*128;
    #pragma unroll
    for (int j=0;j<32;j++) sW[tid + j*256] = src[tid + j*256];
    __syncthreads();
    for (int o=tid; o<3200; o+=256){
        int f = o>>6, n = o&63;
        float acc = 0.f;
        #pragma unroll 8
        for (int d=0; d<128; d++)
            acc += sWin[f*128+d] * __half2float(sW[n*128+d]);
        g_U[(t*50+f)*512 + n0 + n] = acc;
    }
}

// ---------------- k_tg: grid 256 ----------------
__global__ void k_tg(){
    __shared__ float sU[8*512];
    int b = blockIdx.x, tid = threadIdx.x;
    int t = b>>4, which = (b>>3)&1, av0 = (b&7)*32;
    for (int i=tid; i<4096; i+=256)
        sU[i] = g_U[(t*50 + 32 + which*8 + (i>>9))*512 + (i&511)];
    float s1 = g_s1[t];
    __half* dst = (which ? g_T1h : g_T1g) + ((size_t)t<<17) + (size_t)av0*512;
    __syncthreads();
    for (int o=tid; o<16384; o+=256){
        int av = av0 + (o>>9), n = o&511;
        float acc = 0.f;
        #pragma unroll
        for (int i=0;i<8;i++) if ((av>>i)&1) acc += sU[i*512+n];
        dst[o] = __float2half(s1*acc);
    }
}

// ---------------- k_tfc ----------------
__global__ void k_tfc(const float* __restrict__ oe){
    int t = blockIdx.x, tid = threadIdx.x;
    float s1 = g_s1[t];
    for (int o=tid; o<8192; o+=256){
        int n = o&511, cc = (o>>9)&1, opv = o>>10;
        float acc = g_U[(t*50+49)*512+n];
        if (cc) acc += g_U[(t*50+48)*512+n];
        #pragma unroll 8
        for (int j=0;j<32;j++)
            acc += oe[opv*32+j] * g_U[(t*50+j)*512+n];
        g_T1fc[t*8192 + o] = __float2half(s1*acc);
    }
}

// ---------------- k_route ----------------
__global__ void k_route(const int* __restrict__ op, const int* __restrict__ a,
                        const int* __restrict__ b, const int* __restrict__ c,
                        float* __restrict__ outIdx){
    __shared__ float sLf[NOPS*NT], sLg[256*NT], sLh[256*NT], sLc[NT], sLb[NT];
    __shared__ float sP[NT]; __shared__ int sC[NT]; __shared__ int sBase[NT];
    int tid = threadIdx.x;
    int lane = tid & 31;
    for (int i=tid;i<256*NT;i+=256){ sLg[i]=g_Lg[i]; sLh[i]=g_Lh[i]; }
    for (int i=tid;i<NOPS*NT;i+=256) sLf[i]=g_Lf[i];
    if (tid<NT){ sLc[tid]=g_Lc[tid]; sLb[tid]=g_Lb[tid]; sP[tid]=0.f; sC[tid]=0; }
    __syncthreads();
    int i = blockIdx.x*256+tid;
    int opv=op[i], av=a[i], bv=b[i]; float cv=(float)c[i];
    float l[NT]; float mx=-1e30f; int best=0;
    #pragma unroll
    for (int t=0;t<NT;t++){
        float v = sLf[opv*NT+t]+sLg[av*NT+t]+sLh[bv*NT+t]+cv*sLc[t]+sLb[t];
        l[t]=v;
        if (v>mx){mx=v;best=t;}
    }
    float den=0.f;
    #pragma unroll
    for (int t=0;t<NT;t++){ l[t]=__expf(l[t]-mx); den+=l[t]; }
    float inv = 1.f/den;
    #pragma unroll
    for (int t=0;t<NT;t++){
        float v = l[t]*inv;
        #pragma unroll
        for (int o=16;o;o>>=1) v += __shfl_xor_sync(0xffffffffu, v, o);
        if (lane==0) atomicAdd(&sP[t], v);
    }
    int rank = atomicAdd(&sC[best], 1);
    g_gate[i]=inv; outIdx[i]=(float)best;
    __syncthreads();
    if (tid<NT){
        sBase[tid] = atomicAdd(&g_fill[tid], sC[tid]);
        atomicAdd(&g_sumP[tid], (double)sP[tid]);
    }
    __syncthreads();
    g_src[best*TSTR + sBase[best] + rank] = i;
}

// ---------------- k_part ----------------
__global__ void k_part(){
    __shared__ int pc[NT], po_[NT];
    int tid=threadIdx.x;
    if (tid<NT) pc[tid] = g_fill[tid];
    __syncthreads();
    if (tid==0){
        int nb=0;
        for (int t=0;t<NT;t++){ po_[t]=nb; nb += (pc[t]+MROWS-1)/MROWS; }
        g_nblocks = nb;
    }
    __syncthreads();
    for (int t=0;t<NT;t++){
        int bl = (pc[t]+MROWS-1)/MROWS;
        for (int bi=tid; bi<bl; bi+=256){ g_bmT[po_[t]+bi]=t; g_bmR[po_[t]+bi]=t*TSTR + bi*MROWS; }
        int cnt=pc[t]; int pad = bl*MROWS;
        for (int p=cnt+tid; p<pad; p+=256) g_src[t*TSTR+p] = -1;
    }
}

// ---------------- k_ffn: warp-specialized producer/consumer ----------------
__global__ void __launch_bounds__(256,2) k_ffn(
    const int* __restrict__ op, const int* __restrict__ aIn,
    const int* __restrict__ bIn, const int* __restrict__ cIn,
    const float* __restrict__ bh1,
    const float* __restrict__ Wh2, const float* __restrict__ bh2,
    float* __restrict__ outR)
{
    extern __shared__ __half sm[];
    __half* sG0 = sm;                       // [128][SLDH]
    __half* sG1 = sm + 128*SLDH;            // [128][SLDH]
    __half* sW0 = sm + 256*SLDH;            // [64][SLDH]
    __half* sW1 = sW0 + 64*SLDH;            // [64][SLDH]
    __shared__ float sGate[MROWS];
    __shared__ int   sSrc[MROWS];
    __shared__ int   sAV[MROWS], sBV[MROWS], sOC[MROWS];
    __shared__ float sWh2[512], sbh1[64], sbh2[8];

    int bid = blockIdx.x;
    if (bid >= g_nblocks) return;
    int t  = g_bmT[bid], r0 = g_bmR[bid];
    int tid = threadIdx.x;
    int wid = tid>>5, lane = tid&31;

    // ---- per-row caches + small params ----
    if (tid < 128){
        int token = g_src[r0+tid];
        sSrc[tid] = token;
        if (token>=0){
            sGate[tid] = g_gate[token];
            sAV[tid] = aIn[token];
            sBV[tid] = bIn[token];
            sOC[tid] = (t*8 + op[token])*2 + cIn[token];
        } else {
            sGate[tid]=0.f; sAV[tid]=0; sBV[tid]=0; sOC[tid]=t*16;
        }
    }
    for (int i=tid;i<512;i+=256) sWh2[i]=Wh2[i];
    if (tid<64) sbh1[tid]=bh1[tid];
    if (tid<8)  sbh2[tid]=bh2[tid];
    __syncthreads();

    uint32_t gbuf[2] = { smem_u32(sG0), smem_u32(sG1) };
    uint32_t wbuf[2] = { smem_u32(sW0), smem_u32(sW1) };

    if (wid < 4){
        // ================= PRODUCER =================
        int lt4 = lane>>3, lc8 = lane&7;
        const __half2 C0 = __floats2half2_rn(0.044715f, 0.044715f);
        const __half2 C1 = __floats2half2_rn(0.7978845608f, 0.7978845608f);
        const __half2 ONE = __floats2half2_rn(1.f, 1.f);
        const __half2 HLF = __floats2half2_rn(0.5f, 0.5f);
        for (int ch=0; ch<4; ch++){
            int buf = ch&1;
            if (ch>=2) BAR_SYNC2(3+buf);
            __half* gdst = buf ? sG1 : sG0;
            #pragma unroll
            for (int it=0; it<8; it++){
                int row = wid*32 + it*4 + lt4;
                int token = sSrc[row];
                __half* dst = gdst + row*SLDH + lc8*8;
                if (token>=0){
                    const __half* pg = g_T1g + ((((size_t)(t<<8)+sAV[row])<<9) + ch*128 + lc8*8);
                    const __half* ph = g_T1h + ((((size_t)(t<<8)+sBV[row])<<9) + ch*128 + lc8*8);
                    const __half* pf = g_T1fc + (((size_t)sOC[row]<<9) + ch*128 + lc8*8);
                    #pragma unroll
                    for (int seg=0; seg<2; seg++){
                        int off = seg*64;
                        uint4 va = *(const uint4*)(pg+off);
                        uint4 vb = *(const uint4*)(ph+off);
                        uint4 vf = *(const uint4*)(pf+off);
                        __half2* ha=(__half2*)&va;
                        __half2* hb=(__half2*)&vb;
                        __half2* hf=(__half2*)&vf;
                        uint4 ou; __half2* ho=(__half2*)&ou;
                        #pragma unroll
                        for (int q=0;q<4;q++){
                            __half2 v  = __hadd2(__hadd2(ha[q],hb[q]), hf[q]);
                            __half2 v2 = __hmul2(v,v);
                            __half2 v3 = __hmul2(v2,v);
                            __half2 in2= __hfma2(v3, C0, v);
                            __half2 u  = __hmul2(in2, C1);
                            uint32_t ur = *(uint32_t*)&u, tr;
                            asm("tanh.approx.f16x2 %0, %1;" : "=r"(tr) : "r"(ur));
                            __half2 th = *(__half2*)&tr;
                            __half2 onep = __hadd2(th, ONE);
                            __half2 hv = __hmul2(v, HLF);
                            ho[q] = __hmul2(hv, onep);
                        }
                        *(uint4*)(dst+off) = ou;
                    }
                } else {
                    uint4 z = make_uint4(0,0,0,0);
                    *(uint4*)(dst) = z;
                    *(uint4*)(dst+64) = z;
                }
            }
            BAR_ARRIVE2(1+buf);
        }
    } else {
        // ================= CONSUMER =================
        int cm = wid-4;
        int ctid = cm*32 + lane;
        int grp = lane>>2, tq = lane&3;
        uint32_t aoff  = (uint32_t)((lane&15)*SLDH + (lane>>4)*8)*2;
        uint32_t boff4 = (uint32_t)(((lane&7) + ((lane>>4)<<3))*SLDH + ((lane>>3)&1)*8)*2;
        const __half* Wcp = g_Wch + t*32768;

        // prefetch Wc chunk 0
        #pragma unroll
        for (int j=0;j<8;j++){
            int i = ctid + j*128;
            int row = i>>4, ck = i&15;
            cpa16(wbuf[0] + (uint32_t)(row*SLDH + ck*8)*2, Wcp + row*512 + ck*8);
        }
        cpa_commit();

        float c2[2][8][4];
        #pragma unroll
        for(int mt=0;mt<2;mt++)
            #pragma unroll
            for(int nt=0;nt<8;nt++)
                #pragma unroll
                for(int e=0;e<4;e++) c2[mt][nt][e]=0.f;

        for (int ch=0; ch<4; ch++){
            int buf = ch&1;
            cpa_wait0();
            BAR_SYNC_C();              // Wc[ch] visible to all consumers
            BAR_SYNC2(1+buf);          // G[buf] full
            if (ch<3){
                const __half* src = Wcp + (ch+1)*128;
                #pragma unroll
                for (int j=0;j<8;j++){
                    int i = ctid + j*128;
                    int row = i>>4, ck = i&15;
                    cpa16(wbuf[(ch+1)&1] + (uint32_t)(row*SLDH + ck*8)*2, src + row*512 + ck*8);
                }
                cpa_commit();
            }
            uint32_t bg = gbuf[buf], bw = wbuf[buf];
            #pragma unroll
            for (int kk=0;kk<8;kk++){
                uint32_t af[2][4];
                ldsm4(af[0], bg + aoff + (uint32_t)((cm*32)*SLDH + kk*16)*2);
                ldsm4(af[1], bg + aoff + (uint32_t)((cm*32+16)*SLDH + kk*16)*2);
                #pragma unroll
                for (int ntp=0;ntp<4;ntp++){
                    uint32_t bq[4];
                    ldsm4(bq, bw + boff4 + (uint32_t)((ntp*16)*SLDH + kk*16)*2);
                    mma16(c2[0][2*ntp],   af[0], bq);
                    mma16(c2[1][2*ntp],   af[1], bq);
                    mma16(c2[0][2*ntp+1], af[0], bq+2);
                    mma16(c2[1][2*ntp+1], af[1], bq+2);
                }
            }
            if (ch<2) BAR_ARRIVE2(3+buf);
        }

        // ---- epilogue: h = relu(gate*c2 + bh1) -> sH (overwrites sG0; ch3 read sG1) ----
        float* sH = (float*)sG0;   // [128][66]
        #pragma unroll
        for (int mt=0;mt<2;mt++){
            int row0 = cm*32+mt*16+grp;
            float ga = sGate[row0], gb = sGate[row0+8];
            #pragma unroll
            for (int nt=0;nt<8;nt++){
                int col = nt*8+2*tq;
                sH[row0*66+col]       = fmaxf(ga*c2[mt][nt][0]+sbh1[col],   0.f);
                sH[row0*66+col+1]     = fmaxf(ga*c2[mt][nt][1]+sbh1[col+1], 0.f);
                sH[(row0+8)*66+col]   = fmaxf(gb*c2[mt][nt][2]+sbh1[col],   0.f);
                sH[(row0+8)*66+col+1] = fmaxf(gb*c2[mt][nt][3]+sbh1[col+1], 0.f);
            }
        }
    }
    __syncthreads();
    // ---- final 64->8 + sigmoid (2 threads/row, all 256 threads) ----
    {
        float* sH = (float*)sG0;
        int row = tid>>1, c0 = (tid&1)*4;
        int token = sSrc[row];
        if (token>=0){
            float acc0=sbh2[c0], acc1=sbh2[c0+1], acc2=sbh2[c0+2], acc3=sbh2[c0+3];
            #pragma unroll 8
            for (int k2=0;k2<64;k2++){
                float hv = sH[row*66+k2];
                acc0 += hv*sWh2[k2*8+c0];
                acc1 += hv*sWh2[k2*8+c0+1];
                acc2 += hv*sWh2[k2*8+c0+2];
                acc3 += hv*sWh2[k2*8+c0+3];
            }
            float* o = outR + (size_t)token*8 + c0;
            o[0] = 1.f/(1.f+__expf(-acc0));
            o[1] = 1.f/(1.f+__expf(-acc1));
            o[2] = 1.f/(1.f+__expf(-acc2));
            o[3] = 1.f/(1.f+__expf(-acc3));
        }
    }
}

// ---------------- k_aux ----------------
__global__ void k_aux(float* __restrict__ aux){
    if (threadIdx.x==0){
        double sp=0.0, cp[4]={0,0,0,0};
        for (int t=0;t<NT;t++){
            double frac = (double)g_fill[t]/(double)BTOK;
            double mp = g_sumP[t]/(double)BTOK;
            sp += frac*mp;
            cp[t>>2] += mp;
        }
        double sparsity = 16.0*sp;
        double tern = g_res[0]/1048576.0 + g_res[1]/1048576.0;
        double divv = 0.0;
        for (int i=0;i<4;i++) divv += cp[i]*log(cp[i]+1e-9);
        aux[0] = (float)(0.01*tern + 0.005*sparsity + 0.01*divv);
    }
}

// ---------------- launch ----------------
extern "C" void kernel_launch(void* const* d_in, const int* in_sizes, int n_in,
                              void* d_out, int out_size){
    const int *op=nullptr,*a=nullptr,*b=nullptr,*c=nullptr;
    const float *oe=nullptr,*Win=nullptr,*bin=nullptr,*Wr=nullptr,*W1=nullptr,*W2=nullptr;
    const float *Wh1=nullptr,*bh1=nullptr,*Wh2=nullptr,*bh2=nullptr;
    int nb_=0, nw=0;
    for (int i=0;i<n_in;i++){
        int s = in_sizes[i]; void* p = (void*)d_in[i];
        switch(s){
            case BTOK:
                if(nb_==0) op=(const int*)p; else if(nb_==1) a=(const int*)p;
                else if(nb_==2) b=(const int*)p; else c=(const int*)p;
                nb_++; break;
            case 256:  oe=(const float*)p; break;
            case 6272: Win=(const float*)p; break;
            case 128:  bin=(const float*)p; break;
            case 2048: Wr=(const float*)p; break;
            case 1048576: if(nw==0) W1=(const float*)p; else W2=(const float*)p; nw++; break;
            case 8192: Wh1=(const float*)p; break;
            case 64:   bh1=(const float*)p; break;
            case 512:  Wh2=(const float*)p; break;
            case 8:    bh2=(const float*)p; break;
            default: break;
        }
    }
    float* out = (float*)d_out;
    int smem = 384*SLDH*2;   // sG0+sG1 (256 rows) + sW0+sW1 (128 rows)
    cudaFuncSetAttribute(k_ffn, cudaFuncAttributeMaxDynamicSharedMemorySize, smem);

    k_init<<<1,32>>>();
    k_tables<<<260,256>>>(oe,Win);
    k_lt<<<33,256>>>(Wr,Win,bin);
    k_scalep<<<512,256>>>(W1,W2);
    k_sfin<<<1,32>>>();
    k_quant<<<256,256>>>(W1,W2);
    k_wc<<<256,256>>>(Wh1);
    k_u<<<128,256>>>(Win,bin);
    k_tg<<<256,256>>>();
    k_tfc<<<16,256>>>(oe);
    k_route<<<BTOK/256,256>>>(op,a,b,c,out + (size_t)BTOK*8);
    k_part<<<1,256>>>();
    k_ffn<<<MAXBLK,256,smem>>>(op,a,b,c,bh1,Wh2,bh2,out);
    k_aux<<<1,32>>>(out + (size_t)BTOK*9);
}